// round 1
// baseline (speedup 1.0000x reference)
#include <cuda_runtime.h>
#include <math.h>

// ---------------- problem constants ----------------
#define B_SZ      16384
#define IN_DIM    1024
#define OUT_DIM   1000
#define N_INT     1023     // internal nodes
#define N_LEAF    1024
#define DEPTH     10
#define LAMBDA    1e-3f

// ---------------- scratch (device globals; no allocation allowed) ----------
__device__ float g_s[(size_t)B_SZ * 1024];      // sigmoids, stride 1024 (col 1023 unused)
__device__ float g_path[(size_t)B_SZ * 1024];   // leaf path probs
__device__ float g_Wp[(size_t)N_INT * 1024];    // repacked internal weights (aligned)
__device__ float g_bias[1024];                  // internal biases
__device__ float g_T[1023];                     // sum_b newpath[b, j] per layer (first half)
__device__ float g_U[2046];                     // sum_b lp[b,k]*newpath[b,k>>1]

// ---------------- repack W_internal [1023,1025] -> aligned weights + bias ---
__global__ void repack_kernel(const float* __restrict__ Wi,
                              float* __restrict__ Wp, float* __restrict__ bias) {
    int idx = blockIdx.x * blockDim.x + threadIdx.x;
    if (idx < N_INT * 1024) {
        int n = idx >> 10;
        int k = idx & 1023;
        Wp[idx] = Wi[(size_t)n * 1025 + 1 + k];
    }
    if (idx < N_INT) bias[idx] = Wi[(size_t)idx * 1025];
}

// ---------------- zero the reduction accumulators ----------------
__global__ void zero_kernel(float* __restrict__ t, float* __restrict__ u) {
    int i = blockIdx.x * blockDim.x + threadIdx.x;
    if (i < 1023) t[i] = 0.0f;
    if (i < 2046) u[i] = 0.0f;
}

// ---------------- tiled SGEMM NT: C[M,N] = A[M,K] * B[N,K]^T ----------------
// BM=BN=128, BK=8, 256 threads, 8x8 per thread. M % 128 == 0, K % 8 == 0.
// SIG: epilogue = sigmoid(acc + bias[n]).
#define BM 128
#define BN 128
#define BK 8

template<bool SIG>
__global__ void __launch_bounds__(256, 2)
sgemm_nt_kernel(const float* __restrict__ A,
                const float* __restrict__ Bm,
                const float* __restrict__ bias,
                float* __restrict__ C, int ldc,
                int K, int Nvalid) {
    __shared__ float As[BK][BM];
    __shared__ float Bs[BK][BN];

    const int tid  = threadIdx.x;
    const int arow = tid >> 1;          // 0..127
    const int ac4  = (tid & 1) * 4;     // 0 or 4 (K offset of float4)
    const int trow = tid >> 4;          // 0..15 -> m sub-tile
    const int tcol = tid & 15;          // 0..15 -> n sub-tile

    const size_t a_base = ((size_t)blockIdx.y * BM + arow) * (size_t)K + ac4;
    const int    b_row  = blockIdx.x * BN + arow;
    const size_t b_base = (size_t)b_row * (size_t)K + ac4;
    const bool   b_ok   = (b_row < Nvalid);

    float acc[8][8];
#pragma unroll
    for (int i = 0; i < 8; i++)
#pragma unroll
        for (int j = 0; j < 8; j++) acc[i][j] = 0.0f;

    for (int k0 = 0; k0 < K; k0 += BK) {
        float4 av = *(const float4*)(A + a_base + k0);
        float4 bv = b_ok ? *(const float4*)(Bm + b_base + k0)
                         : make_float4(0.f, 0.f, 0.f, 0.f);
        As[ac4 + 0][arow] = av.x;
        As[ac4 + 1][arow] = av.y;
        As[ac4 + 2][arow] = av.z;
        As[ac4 + 3][arow] = av.w;
        Bs[ac4 + 0][arow] = bv.x;
        Bs[ac4 + 1][arow] = bv.y;
        Bs[ac4 + 2][arow] = bv.z;
        Bs[ac4 + 3][arow] = bv.w;
        __syncthreads();

#pragma unroll
        for (int k = 0; k < BK; k++) {
            float4 a0 = *(const float4*)&As[k][trow * 8];
            float4 a1 = *(const float4*)&As[k][trow * 8 + 4];
            float4 b0 = *(const float4*)&Bs[k][tcol * 8];
            float4 b1 = *(const float4*)&Bs[k][tcol * 8 + 4];
            float ra[8] = {a0.x, a0.y, a0.z, a0.w, a1.x, a1.y, a1.z, a1.w};
            float rb[8] = {b0.x, b0.y, b0.z, b0.w, b1.x, b1.y, b1.z, b1.w};
#pragma unroll
            for (int i = 0; i < 8; i++)
#pragma unroll
                for (int j = 0; j < 8; j++)
                    acc[i][j] = fmaf(ra[i], rb[j], acc[i][j]);
        }
        __syncthreads();
    }

    const int m0 = blockIdx.y * BM + trow * 8;
    const int n0 = blockIdx.x * BN + tcol * 8;
#pragma unroll
    for (int i = 0; i < 8; i++) {
#pragma unroll
        for (int j = 0; j < 8; j++) {
            int n = n0 + j;
            if (n < Nvalid) {
                float v = acc[i][j];
                if (SIG) {
                    v += bias[n];
                    v = 1.0f / (1.0f + expf(-v));
                }
                C[(size_t)(m0 + i) * ldc + n] = v;
            }
        }
    }
}

// ---------------- path + regularizer partial sums ----------------
// One block of 256 threads handles 64 consecutive samples.
#define SAMPLES_PER_BLOCK 64

__global__ void __launch_bounds__(256)
path_kernel(const float* __restrict__ s_g, float* __restrict__ path_g,
            float* __restrict__ gT, float* __restrict__ gU) {
    __shared__ float s_sh[1024];
    __shared__ float bufA[1024];
    __shared__ float bufB[1024];
    __shared__ float Tacc[1023];
    __shared__ float Uacc[2046];

    const int tid = threadIdx.x;
    for (int i = tid; i < 1023; i += 256) Tacc[i] = 0.0f;
    for (int i = tid; i < 2046; i += 256) Uacc[i] = 0.0f;

    const int base = blockIdx.x * SAMPLES_PER_BLOCK;

    for (int s = 0; s < SAMPLES_PER_BLOCK; s++) {
        const int b = base + s;
        __syncthreads();  // previous sample fully consumed
        for (int i = tid; i < 1024; i += 256)
            s_sh[i] = s_g[(size_t)b * 1024 + i];
        if (tid == 0) bufA[0] = 1.0f;
        __syncthreads();

        float* cur = bufA;
        float* nxt = bufB;
        int toff = 0, uoff = 0;

#pragma unroll
        for (int d = 0; d < DEPTH; d++) {
            const int nout = 2 << d;        // 2^{d+1}
            const int nbase = (1 << d) - 1; // layer-d node base
            for (int k = tid; k < nout; k += 256) {
                float sv = s_sh[nbase + (k >> 1)];
                float lp = (k & 1) ? (1.0f - sv) : sv;
                nxt[k] = cur[k >> 1] * lp;
            }
            __syncthreads();
            // regularizer partials: each smem index owned by a fixed tid -> race-free
            for (int k = tid; k < nout; k += 256) {
                float sv = s_sh[nbase + (k >> 1)];
                float lp = (k & 1) ? (1.0f - sv) : sv;
                Uacc[uoff + k] += lp * nxt[k >> 1];
            }
            const int nhalf = 1 << d;
            for (int j = tid; j < nhalf; j += 256) Tacc[toff + j] += nxt[j];
            toff += nhalf;
            uoff += nout;
            float* t = cur; cur = nxt; nxt = t;
        }

        // cur now holds 1024 leaf probabilities (valid: post sync of level 9)
        for (int l = tid; l < 1024; l += 256)
            path_g[(size_t)b * 1024 + l] = cur[l];
    }

    __syncthreads();
    for (int i = tid; i < 1023; i += 256) atomicAdd(&gT[i], Tacc[i]);
    for (int i = tid; i < 2046; i += 256) atomicAdd(&gU[i], Uacc[i]);
}

// ---------------- regularizer scalar ----------------
__global__ void reg_kernel(const float* __restrict__ gT, const float* __restrict__ gU,
                           float* __restrict__ out) {
    float local = 0.0f;
    int toff = 0, uoff = 0;
#pragma unroll
    for (int d = 0; d < DEPTH; d++) {
        const int nout = 2 << d;
        const float factor = LAMBDA * exp2f(-(float)d);
        for (int k = threadIdx.x; k < nout; k += 256) {
            float den = gT[toff + (k >> 1)] + 1e-8f;
            float alpha = gU[uoff + k] / den;
            local += factor * (-0.5f) * (logf(alpha) + logf(1.0f - alpha));
        }
        toff += (1 << d);
        uoff += nout;
    }
    __shared__ float red[256];
    red[threadIdx.x] = local;
    __syncthreads();
    for (int s = 128; s > 0; s >>= 1) {
        if (threadIdx.x < s) red[threadIdx.x] += red[threadIdx.x + s];
        __syncthreads();
    }
    if (threadIdx.x == 0) out[0] = red[0];
}

// ---------------- launch ----------------
extern "C" void kernel_launch(void* const* d_in, const int* in_sizes, int n_in,
                              void* d_out, int out_size) {
    const float* X  = (const float*)d_in[0];   // [16384, 1024]
    const float* Wi = (const float*)d_in[1];   // [1023, 1025]
    const float* Wl = (const float*)d_in[2];   // [1000, 1024]
    float* out = (float*)d_out;

    float *s_p, *path_p, *wp_p, *bias_p, *t_p, *u_p;
    cudaGetSymbolAddress((void**)&s_p,    g_s);
    cudaGetSymbolAddress((void**)&path_p, g_path);
    cudaGetSymbolAddress((void**)&wp_p,   g_Wp);
    cudaGetSymbolAddress((void**)&bias_p, g_bias);
    cudaGetSymbolAddress((void**)&t_p,    g_T);
    cudaGetSymbolAddress((void**)&u_p,    g_U);

    // 1. repack internal weights (aligned) + bias
    {
        int total = N_INT * 1024;
        repack_kernel<<<(total + 255) / 256, 256>>>(Wi, wp_p, bias_p);
    }
    // 2. zero reduction accumulators
    zero_kernel<<<8, 256>>>(t_p, u_p);

    // 3. GEMM1 + sigmoid: g_s = sigmoid(X @ Wp^T + bias)
    {
        dim3 grid((N_INT + BN - 1) / BN, B_SZ / BM);  // (8, 128)
        sgemm_nt_kernel<true><<<grid, 256>>>(X, wp_p, bias_p, s_p, 1024, IN_DIM, N_INT);
    }

    // 4. path probs + regularizer partial sums
    path_kernel<<<B_SZ / SAMPLES_PER_BLOCK, 256>>>(s_p, path_p, t_p, u_p);

    // 5. GEMM2: predictions = path @ W_leaf^T -> d_out[0 .. B*OUT_DIM)
    {
        dim3 grid((OUT_DIM + BN - 1) / BN, B_SZ / BM);  // (8, 128)
        sgemm_nt_kernel<false><<<grid, 256>>>(path_p, Wl, nullptr, out, OUT_DIM, N_LEAF, OUT_DIM);
    }

    // 6. regularizer scalar -> last output element
    reg_kernel<<<1, 256>>>(t_p, u_p, out + (out_size - 1));
}

// round 2
// speedup vs baseline: 1.0012x; 1.0012x over previous
#include <cuda_runtime.h>
#include <math.h>

// ---------------- problem constants ----------------
#define B_SZ      16384
#define IN_DIM    1024
#define OUT_DIM   1000
#define N_INT     1023     // internal nodes
#define N_LEAF    1024
#define DEPTH     10
#define LAMBDA    1e-3f

// ---------------- scratch (device globals; no allocation allowed) ----------
__device__ float g_s[(size_t)B_SZ * 1024];      // sigmoids, stride 1024 (col 1023 unused)
__device__ float g_path[(size_t)B_SZ * 1024];   // leaf path probs
__device__ float g_Wp[(size_t)N_INT * 1024];    // repacked internal weights (aligned)
__device__ float g_bias[1024];                  // internal biases
__device__ float g_T[1023];                     // sum_b newpath[b, j] per layer (first half)
__device__ float g_U[2046];                     // sum_b lp[b,k]*newpath[b,k>>1]

// ---------------- repack W_internal [1023,1025] -> aligned weights + bias ---
__global__ void repack_kernel(const float* __restrict__ Wi,
                              float* __restrict__ Wp, float* __restrict__ bias) {
    int idx = blockIdx.x * blockDim.x + threadIdx.x;
    if (idx < N_INT * 1024) {
        int n = idx >> 10;
        int k = idx & 1023;
        Wp[idx] = Wi[(size_t)n * 1025 + 1 + k];
    }
    if (idx < N_INT) bias[idx] = Wi[(size_t)idx * 1025];
}

// ---------------- zero the reduction accumulators ----------------
__global__ void zero_kernel(float* __restrict__ t, float* __restrict__ u) {
    int i = blockIdx.x * blockDim.x + threadIdx.x;
    if (i < 1023) t[i] = 0.0f;
    if (i < 2046) u[i] = 0.0f;
}

// ---------------- tiled SGEMM NT: C[M,N] = A[M,K] * B[N,K]^T ----------------
// BM=BN=128, BK=8, 256 threads, 8x8 per thread. M % 128 == 0, K % 8 == 0.
// SIG: epilogue = sigmoid(acc + bias[n]).
#define BM 128
#define BN 128
#define BK 8

template<bool SIG>
__global__ void __launch_bounds__(256, 2)
sgemm_nt_kernel(const float* __restrict__ A,
                const float* __restrict__ Bm,
                const float* __restrict__ bias,
                float* __restrict__ C, int ldc,
                int K, int Nvalid) {
    __shared__ float As[BK][BM];
    __shared__ float Bs[BK][BN];

    const int tid  = threadIdx.x;
    const int arow = tid >> 1;          // 0..127
    const int ac4  = (tid & 1) * 4;     // 0 or 4 (K offset of float4)
    const int trow = tid >> 4;          // 0..15 -> m sub-tile
    const int tcol = tid & 15;          // 0..15 -> n sub-tile

    const size_t a_base = ((size_t)blockIdx.y * BM + arow) * (size_t)K + ac4;
    const int    b_row  = blockIdx.x * BN + arow;
    const size_t b_base = (size_t)b_row * (size_t)K + ac4;
    const bool   b_ok   = (b_row < Nvalid);

    float acc[8][8];
#pragma unroll
    for (int i = 0; i < 8; i++)
#pragma unroll
        for (int j = 0; j < 8; j++) acc[i][j] = 0.0f;

    for (int k0 = 0; k0 < K; k0 += BK) {
        float4 av = *(const float4*)(A + a_base + k0);
        float4 bv = b_ok ? *(const float4*)(Bm + b_base + k0)
                         : make_float4(0.f, 0.f, 0.f, 0.f);
        As[ac4 + 0][arow] = av.x;
        As[ac4 + 1][arow] = av.y;
        As[ac4 + 2][arow] = av.z;
        As[ac4 + 3][arow] = av.w;
        Bs[ac4 + 0][arow] = bv.x;
        Bs[ac4 + 1][arow] = bv.y;
        Bs[ac4 + 2][arow] = bv.z;
        Bs[ac4 + 3][arow] = bv.w;
        __syncthreads();

#pragma unroll
        for (int k = 0; k < BK; k++) {
            float4 a0 = *(const float4*)&As[k][trow * 8];
            float4 a1 = *(const float4*)&As[k][trow * 8 + 4];
            float4 b0 = *(const float4*)&Bs[k][tcol * 8];
            float4 b1 = *(const float4*)&Bs[k][tcol * 8 + 4];
            float ra[8] = {a0.x, a0.y, a0.z, a0.w, a1.x, a1.y, a1.z, a1.w};
            float rb[8] = {b0.x, b0.y, b0.z, b0.w, b1.x, b1.y, b1.z, b1.w};
#pragma unroll
            for (int i = 0; i < 8; i++)
#pragma unroll
                for (int j = 0; j < 8; j++)
                    acc[i][j] = fmaf(ra[i], rb[j], acc[i][j]);
        }
        __syncthreads();
    }

    const int m0 = blockIdx.y * BM + trow * 8;
    const int n0 = blockIdx.x * BN + tcol * 8;
#pragma unroll
    for (int i = 0; i < 8; i++) {
#pragma unroll
        for (int j = 0; j < 8; j++) {
            int n = n0 + j;
            if (n < Nvalid) {
                float v = acc[i][j];
                if (SIG) {
                    v += bias[n];
                    v = 1.0f / (1.0f + expf(-v));
                }
                C[(size_t)(m0 + i) * ldc + n] = v;
            }
        }
    }
}

// ---------------- path + regularizer partial sums ----------------
// One block of 256 threads handles 64 consecutive samples.
#define SAMPLES_PER_BLOCK 64

__global__ void __launch_bounds__(256)
path_kernel(const float* __restrict__ s_g, float* __restrict__ path_g,
            float* __restrict__ gT, float* __restrict__ gU) {
    __shared__ float s_sh[1024];
    __shared__ float bufA[1024];
    __shared__ float bufB[1024];
    __shared__ float Tacc[1023];
    __shared__ float Uacc[2046];

    const int tid = threadIdx.x;
    for (int i = tid; i < 1023; i += 256) Tacc[i] = 0.0f;
    for (int i = tid; i < 2046; i += 256) Uacc[i] = 0.0f;

    const int base = blockIdx.x * SAMPLES_PER_BLOCK;

    for (int s = 0; s < SAMPLES_PER_BLOCK; s++) {
        const int b = base + s;
        __syncthreads();  // previous sample fully consumed
        for (int i = tid; i < 1024; i += 256)
            s_sh[i] = s_g[(size_t)b * 1024 + i];
        if (tid == 0) bufA[0] = 1.0f;
        __syncthreads();

        float* cur = bufA;
        float* nxt = bufB;
        int toff = 0, uoff = 0;

#pragma unroll
        for (int d = 0; d < DEPTH; d++) {
            const int nout = 2 << d;        // 2^{d+1}
            const int nbase = (1 << d) - 1; // layer-d node base
            for (int k = tid; k < nout; k += 256) {
                float sv = s_sh[nbase + (k >> 1)];
                float lp = (k & 1) ? (1.0f - sv) : sv;
                nxt[k] = cur[k >> 1] * lp;
            }
            __syncthreads();
            // regularizer partials: each smem index owned by a fixed tid -> race-free
            for (int k = tid; k < nout; k += 256) {
                float sv = s_sh[nbase + (k >> 1)];
                float lp = (k & 1) ? (1.0f - sv) : sv;
                Uacc[uoff + k] += lp * nxt[k >> 1];
            }
            const int nhalf = 1 << d;
            for (int j = tid; j < nhalf; j += 256) Tacc[toff + j] += nxt[j];
            toff += nhalf;
            uoff += nout;
            float* t = cur; cur = nxt; nxt = t;
        }

        // cur now holds 1024 leaf probabilities (valid: post sync of level 9)
        for (int l = tid; l < 1024; l += 256)
            path_g[(size_t)b * 1024 + l] = cur[l];
    }

    __syncthreads();
    for (int i = tid; i < 1023; i += 256) atomicAdd(&gT[i], Tacc[i]);
    for (int i = tid; i < 2046; i += 256) atomicAdd(&gU[i], Uacc[i]);
}

// ---------------- regularizer scalar ----------------
__global__ void reg_kernel(const float* __restrict__ gT, const float* __restrict__ gU,
                           float* __restrict__ out) {
    float local = 0.0f;
    int toff = 0, uoff = 0;
#pragma unroll
    for (int d = 0; d < DEPTH; d++) {
        const int nout = 2 << d;
        const float factor = LAMBDA * exp2f(-(float)d);
        for (int k = threadIdx.x; k < nout; k += 256) {
            float den = gT[toff + (k >> 1)] + 1e-8f;
            float alpha = gU[uoff + k] / den;
            local += factor * (-0.5f) * (logf(alpha) + logf(1.0f - alpha));
        }
        toff += (1 << d);
        uoff += nout;
    }
    __shared__ float red[256];
    red[threadIdx.x] = local;
    __syncthreads();
    for (int s = 128; s > 0; s >>= 1) {
        if (threadIdx.x < s) red[threadIdx.x] += red[threadIdx.x + s];
        __syncthreads();
    }
    if (threadIdx.x == 0) out[0] = red[0];
}

// ---------------- launch ----------------
extern "C" void kernel_launch(void* const* d_in, const int* in_sizes, int n_in,
                              void* d_out, int out_size) {
    const float* X  = (const float*)d_in[0];   // [16384, 1024]
    const float* Wi = (const float*)d_in[1];   // [1023, 1025]
    const float* Wl = (const float*)d_in[2];   // [1000, 1024]
    float* out = (float*)d_out;

    float *s_p, *path_p, *wp_p, *bias_p, *t_p, *u_p;
    cudaGetSymbolAddress((void**)&s_p,    g_s);
    cudaGetSymbolAddress((void**)&path_p, g_path);
    cudaGetSymbolAddress((void**)&wp_p,   g_Wp);
    cudaGetSymbolAddress((void**)&bias_p, g_bias);
    cudaGetSymbolAddress((void**)&t_p,    g_T);
    cudaGetSymbolAddress((void**)&u_p,    g_U);

    // 1. repack internal weights (aligned) + bias
    {
        int total = N_INT * 1024;
        repack_kernel<<<(total + 255) / 256, 256>>>(Wi, wp_p, bias_p);
    }
    // 2. zero reduction accumulators
    zero_kernel<<<8, 256>>>(t_p, u_p);

    // 3. GEMM1 + sigmoid: g_s = sigmoid(X @ Wp^T + bias)
    {
        dim3 grid((N_INT + BN - 1) / BN, B_SZ / BM);  // (8, 128)
        sgemm_nt_kernel<true><<<grid, 256>>>(X, wp_p, bias_p, s_p, 1024, IN_DIM, N_INT);
    }

    // 4. path probs + regularizer partial sums
    path_kernel<<<B_SZ / SAMPLES_PER_BLOCK, 256>>>(s_p, path_p, t_p, u_p);

    // 5. GEMM2: predictions = path @ W_leaf^T -> d_out[0 .. B*OUT_DIM)
    {
        dim3 grid((OUT_DIM + BN - 1) / BN, B_SZ / BM);  // (8, 128)
        sgemm_nt_kernel<false><<<grid, 256>>>(path_p, Wl, nullptr, out, OUT_DIM, N_LEAF, OUT_DIM);
    }

    // 6. regularizer scalar -> last output element
    reg_kernel<<<1, 256>>>(t_p, u_p, out + (out_size - 1));
}

// round 4
// speedup vs baseline: 2.7295x; 2.7263x over previous
#include <cuda_runtime.h>
#include <cuda_bf16.h>
#include <cstdint>
#include <math.h>

// ---------------- problem constants ----------------
#define B_SZ      16384
#define KDIM      1024
#define OUT_DIM   1000
#define N_INT     1023
#define DEPTH     10
#define LAMBDA    1e-3f

// ---------------- scratch (device globals) ----------------
__device__ __nv_bfloat16 g_Xhi[(size_t)B_SZ * KDIM];
__device__ __nv_bfloat16 g_Xlo[(size_t)B_SZ * KDIM];
__device__ __nv_bfloat16 g_Phi[(size_t)B_SZ * KDIM];
__device__ __nv_bfloat16 g_Plo[(size_t)B_SZ * KDIM];
__device__ __nv_bfloat16 g_Whi[(size_t)KDIM * KDIM];
__device__ __nv_bfloat16 g_Wlo[(size_t)KDIM * KDIM];
__device__ __nv_bfloat16 g_Lhi[(size_t)KDIM * KDIM];
__device__ __nv_bfloat16 g_Llo[(size_t)KDIM * KDIM];
__device__ float g_s[(size_t)B_SZ * KDIM];
__device__ float g_bias[KDIM];
__device__ float g_T[1023];
__device__ float g_U[2046];

// ---------------- PTX helpers (sm_80-class features only) ----------------
__device__ __forceinline__ uint32_t smem_u32(const void* p) {
    uint32_t a;
    asm("{ .reg .u64 t; cvta.to.shared.u64 t, %1; cvt.u32.u64 %0, t; }" : "=r"(a) : "l"(p));
    return a;
}

#define CP_ASYNC16(dst, src) \
    asm volatile("cp.async.cg.shared.global [%0], [%1], 16;" :: "r"(dst), "l"(src))
#define CP_COMMIT() asm volatile("cp.async.commit_group;" ::: "memory")
#define CP_WAIT(n)  asm volatile("cp.async.wait_group %0;" :: "n"(n) : "memory")

#define LDMX4(r0, r1, r2, r3, addr) \
    asm volatile("ldmatrix.sync.aligned.m8n8.x4.shared.b16 {%0,%1,%2,%3}, [%4];" \
        : "=r"(r0), "=r"(r1), "=r"(r2), "=r"(r3) : "r"(addr))

#define MMA16816(d, a, b) \
    asm volatile("mma.sync.aligned.m16n8k16.row.col.f32.bf16.bf16.f32 " \
        "{%0,%1,%2,%3}, {%4,%5,%6,%7}, {%8,%9}, {%0,%1,%2,%3};" \
        : "+f"((d)[0]), "+f"((d)[1]), "+f"((d)[2]), "+f"((d)[3]) \
        : "r"((a)[0]), "r"((a)[1]), "r"((a)[2]), "r"((a)[3]), \
          "r"((b)[0]), "r"((b)[1]))

// ---------------- fp32 -> bf16 hi/lo split ----------------
__device__ __forceinline__ void split2(float x, __nv_bfloat16& h, __nv_bfloat16& l) {
    h = __float2bfloat16(x);
    l = __float2bfloat16(x - __bfloat162float(h));
}

__global__ void split_x_kernel(const float* __restrict__ src,
                               __nv_bfloat16* __restrict__ hi,
                               __nv_bfloat16* __restrict__ lo) {
    size_t i = (size_t)blockIdx.x * blockDim.x + threadIdx.x;  // quad index
    float4 v = ((const float4*)src)[i];
    __nv_bfloat16 h0, h1, h2, h3, l0, l1, l2, l3;
    split2(v.x, h0, l0); split2(v.y, h1, l1); split2(v.z, h2, l2); split2(v.w, h3, l3);
    ((__nv_bfloat162*)hi)[2 * i]     = __nv_bfloat162(h0, h1);
    ((__nv_bfloat162*)hi)[2 * i + 1] = __nv_bfloat162(h2, h3);
    ((__nv_bfloat162*)lo)[2 * i]     = __nv_bfloat162(l0, l1);
    ((__nv_bfloat162*)lo)[2 * i + 1] = __nv_bfloat162(l2, l3);
}

__global__ void repack_w_kernel(const float* __restrict__ Wi,
                                __nv_bfloat16* __restrict__ hi,
                                __nv_bfloat16* __restrict__ lo,
                                float* __restrict__ bias) {
    int idx = blockIdx.x * blockDim.x + threadIdx.x;
    if (idx < KDIM * KDIM) {
        int n = idx >> 10, k = idx & 1023;
        float v = (n < N_INT) ? Wi[(size_t)n * 1025 + 1 + k] : 0.0f;
        __nv_bfloat16 h, l; split2(v, h, l);
        hi[idx] = h; lo[idx] = l;
    }
    if (idx < KDIM) bias[idx] = (idx < N_INT) ? Wi[(size_t)idx * 1025] : 0.0f;
}

__global__ void repack_l_kernel(const float* __restrict__ Wl,
                                __nv_bfloat16* __restrict__ hi,
                                __nv_bfloat16* __restrict__ lo) {
    int idx = blockIdx.x * blockDim.x + threadIdx.x;
    if (idx < KDIM * KDIM) {
        int n = idx >> 10, k = idx & 1023;
        float v = (n < OUT_DIM) ? Wl[(size_t)n * KDIM + k] : 0.0f;
        __nv_bfloat16 h, l; split2(v, h, l);
        hi[idx] = h; lo[idx] = l;
    }
}

__global__ void zero_kernel(float* __restrict__ t, float* __restrict__ u) {
    int i = blockIdx.x * blockDim.x + threadIdx.x;
    if (i < 1023) t[i] = 0.0f;
    if (i < 2046) u[i] = 0.0f;
}

// ---------------- mma.sync GEMM: C[M,N] = A * B^T (3-term bf16 emulation) ---
// CTA tile 128x128, BK=32, 3-stage cp.async pipeline, 256 threads (8 warps
// in 4x2), warp tile 32x64 via m16n8k16.
#define ROWB        80                    // 64B data + 16B pad (conflict-free)
#define BUF_BYTES   (128 * ROWB)          // 10240
#define STAGE_BYTES (4 * BUF_BYTES)       // 40960: Ahi, Alo, Bhi, Blo
#define OFF_AHI     0
#define OFF_ALO     BUF_BYTES
#define OFF_BHI     (2 * BUF_BYTES)
#define OFF_BLO     (3 * BUF_BYTES)
#define NCHUNK      32                    // K=1024 / BK=32
#define DYN_SMEM    (3 * STAGE_BYTES + 512)

__device__ __forceinline__ void load_stage(
        const __nv_bfloat16* __restrict__ Ahi, const __nv_bfloat16* __restrict__ Alo,
        const __nv_bfloat16* __restrict__ Bhi, const __nv_bfloat16* __restrict__ Blo,
        int m0, int n0, int chunk, uint32_t sb, int tid) {
    const int r = tid >> 2;
    const int c = tid & 3;
    const int kk = chunk * 32 + c * 8;
    const uint32_t doff = (uint32_t)r * ROWB + (uint32_t)c * 16;
#pragma unroll
    for (int h = 0; h < 2; h++) {
        const int rr = r + h * 64;
        const uint32_t d = sb + doff + (uint32_t)(h * 64 * ROWB);
        CP_ASYNC16(d + OFF_AHI, Ahi + (size_t)(m0 + rr) * KDIM + kk);
        CP_ASYNC16(d + OFF_ALO, Alo + (size_t)(m0 + rr) * KDIM + kk);
        CP_ASYNC16(d + OFF_BHI, Bhi + (size_t)(n0 + rr) * KDIM + kk);
        CP_ASYNC16(d + OFF_BLO, Blo + (size_t)(n0 + rr) * KDIM + kk);
    }
}

template<bool SIG>
__global__ void __launch_bounds__(256, 1)
mma_gemm_kernel(const __nv_bfloat16* __restrict__ Ahi, const __nv_bfloat16* __restrict__ Alo,
                const __nv_bfloat16* __restrict__ Bhi, const __nv_bfloat16* __restrict__ Blo,
                const float* __restrict__ bias, float* __restrict__ C,
                int ldc, int nclip) {
    extern __shared__ char sm[];
    const uint32_t s0 = smem_u32(sm);
    float* bias_sh = (float*)(sm + 3 * STAGE_BYTES);

    const int tid  = threadIdx.x;
    const int lane = tid & 31;
    const int wid  = tid >> 5;
    const int wm   = wid & 3;    // 4 M-warps of 32 rows
    const int wn   = wid >> 2;   // 2 N-warps of 64 cols
    const int m0   = blockIdx.y * 128;
    const int n0   = blockIdx.x * 128;

    if (SIG && tid < 128) bias_sh[tid] = bias[n0 + tid];

    float acc[2][8][4];
#pragma unroll
    for (int mi = 0; mi < 2; mi++)
#pragma unroll
        for (int ni = 0; ni < 8; ni++)
#pragma unroll
            for (int j = 0; j < 4; j++) acc[mi][ni][j] = 0.0f;

    // ldmatrix per-thread address components
    // A frag (m16k16): lanes 0-15 rows 0-15 of k-half 0; lanes 16-31 k-half 1
    const uint32_t a_off = (uint32_t)(wm * 32 + (lane & 15)) * ROWB
                         + (uint32_t)(lane >> 4) * 16;
    // B pair (2 n-frags): r0/r1 = rows n0..n0+7 (k-half 0/1), r2/r3 = rows +8
    const uint32_t b_off = (uint32_t)(wn * 64 + ((lane >> 4) & 1) * 8 + (lane & 7)) * ROWB
                         + (uint32_t)((lane >> 3) & 1) * 16;

    load_stage(Ahi, Alo, Bhi, Blo, m0, n0, 0, s0, tid);               CP_COMMIT();
    load_stage(Ahi, Alo, Bhi, Blo, m0, n0, 1, s0 + STAGE_BYTES, tid); CP_COMMIT();

    for (int cch = 0; cch < NCHUNK; cch++) {
        if (cch + 2 < NCHUNK) {
            load_stage(Ahi, Alo, Bhi, Blo, m0, n0, cch + 2,
                       s0 + (uint32_t)((cch + 2) % 3) * STAGE_BYTES, tid);
            CP_COMMIT();
            CP_WAIT(2);
        } else if (cch + 1 < NCHUNK) {
            CP_WAIT(1);
        } else {
            CP_WAIT(0);
        }
        __syncthreads();

        const uint32_t sb = s0 + (uint32_t)(cch % 3) * STAGE_BYTES;
#pragma unroll
        for (int ks = 0; ks < 2; ks++) {
            uint32_t ah[2][4], al[2][4], bh[8][2], bl[8][2];
#pragma unroll
            for (int mi = 0; mi < 2; mi++) {
                const uint32_t ao = sb + a_off + (uint32_t)(mi * 16 * ROWB) + (uint32_t)(ks * 32);
                LDMX4(ah[mi][0], ah[mi][1], ah[mi][2], ah[mi][3], ao + OFF_AHI);
                LDMX4(al[mi][0], al[mi][1], al[mi][2], al[mi][3], ao + OFF_ALO);
            }
#pragma unroll
            for (int pj = 0; pj < 4; pj++) {
                const uint32_t bo = sb + b_off + (uint32_t)(pj * 16 * ROWB) + (uint32_t)(ks * 32);
                LDMX4(bh[2 * pj][0], bh[2 * pj][1], bh[2 * pj + 1][0], bh[2 * pj + 1][1],
                      bo + OFF_BHI);
                LDMX4(bl[2 * pj][0], bl[2 * pj][1], bl[2 * pj + 1][0], bl[2 * pj + 1][1],
                      bo + OFF_BLO);
            }
#pragma unroll
            for (int mi = 0; mi < 2; mi++)
#pragma unroll
                for (int ni = 0; ni < 8; ni++) {
                    MMA16816(acc[mi][ni], ah[mi], bh[ni]);
                    MMA16816(acc[mi][ni], ah[mi], bl[ni]);
                    MMA16816(acc[mi][ni], al[mi], bh[ni]);
                }
        }
        __syncthreads();
    }

    // epilogue: direct register -> global stores (float2, 8B aligned)
    const int tr = lane >> 2;
    const int tc = (lane & 3) * 2;
#pragma unroll
    for (int mi = 0; mi < 2; mi++) {
#pragma unroll
        for (int ni = 0; ni < 8; ni++) {
            const int row = m0 + wm * 32 + mi * 16 + tr;
            const int col = n0 + wn * 64 + ni * 8 + tc;
            float v0 = acc[mi][ni][0], v1 = acc[mi][ni][1];
            float v2 = acc[mi][ni][2], v3 = acc[mi][ni][3];
            if (SIG) {
                const float b0 = bias_sh[col - n0];
                const float b1 = bias_sh[col - n0 + 1];
                v0 = 1.0f / (1.0f + expf(-(v0 + b0)));
                v1 = 1.0f / (1.0f + expf(-(v1 + b1)));
                v2 = 1.0f / (1.0f + expf(-(v2 + b0)));
                v3 = 1.0f / (1.0f + expf(-(v3 + b1)));
            }
            if (col < nclip) {  // col even, nclip even -> pair never straddles
                *(float2*)&C[(size_t)row * ldc + col]       = make_float2(v0, v1);
                *(float2*)&C[(size_t)(row + 8) * ldc + col] = make_float2(v2, v3);
            }
        }
    }
}

// ---------------- path + regularizer partial sums ----------------
#define SAMPLES_PER_BLOCK 16

__global__ void __launch_bounds__(256)
path_kernel(const float* __restrict__ s_g,
            __nv_bfloat16* __restrict__ phi, __nv_bfloat16* __restrict__ plo,
            float* __restrict__ gT, float* __restrict__ gU) {
    __shared__ float s_sh[1024];
    __shared__ float bufA[1024];
    __shared__ float bufB[1024];
    __shared__ float Tacc[1023];
    __shared__ float Uacc[2046];

    const int tid = threadIdx.x;
    for (int i = tid; i < 1023; i += 256) Tacc[i] = 0.0f;
    for (int i = tid; i < 2046; i += 256) Uacc[i] = 0.0f;

    const int base = blockIdx.x * SAMPLES_PER_BLOCK;

    for (int s = 0; s < SAMPLES_PER_BLOCK; s++) {
        const int b = base + s;
        __syncthreads();
        for (int i = tid; i < 1024; i += 256)
            s_sh[i] = s_g[(size_t)b * 1024 + i];
        if (tid == 0) bufA[0] = 1.0f;
        __syncthreads();

        float* cur = bufA;
        float* nxt = bufB;
        int toff = 0, uoff = 0;

#pragma unroll
        for (int d = 0; d < DEPTH; d++) {
            const int nout = 2 << d;
            const int nbase = (1 << d) - 1;
            for (int k = tid; k < nout; k += 256) {
                float sv = s_sh[nbase + (k >> 1)];
                float lp = (k & 1) ? (1.0f - sv) : sv;
                float nk = cur[k >> 1] * lp;
                nxt[k] = nk;
                // parent-in-new path prob, recomputed locally (no extra barrier)
                int p = k >> 1;
                float svp = s_sh[nbase + (p >> 1)];
                float lpp = (p & 1) ? (1.0f - svp) : svp;
                float pn = cur[p >> 1] * lpp;
                Uacc[uoff + k] += lp * pn;
                if (k < (nout >> 1)) Tacc[toff + k] += nk;
            }
            __syncthreads();
            toff += nout >> 1;
            uoff += nout;
            float* t = cur; cur = nxt; nxt = t;
        }

        for (int l = tid; l < 1024; l += 256) {
            float p = cur[l];
            __nv_bfloat16 h, lo; split2(p, h, lo);
            phi[(size_t)b * 1024 + l] = h;
            plo[(size_t)b * 1024 + l] = lo;
        }
    }

    __syncthreads();
    for (int i = tid; i < 1023; i += 256) atomicAdd(&gT[i], Tacc[i]);
    for (int i = tid; i < 2046; i += 256) atomicAdd(&gU[i], Uacc[i]);
}

// ---------------- regularizer scalar ----------------
__global__ void reg_kernel(const float* __restrict__ gT, const float* __restrict__ gU,
                           float* __restrict__ out) {
    float local = 0.0f;
    int toff = 0, uoff = 0;
#pragma unroll
    for (int d = 0; d < DEPTH; d++) {
        const int nout = 2 << d;
        const float factor = LAMBDA * exp2f(-(float)d);
        for (int k = threadIdx.x; k < nout; k += 256) {
            float den = gT[toff + (k >> 1)] + 1e-8f;
            float alpha = gU[uoff + k] / den;
            local += factor * (-0.5f) * (logf(alpha) + logf(1.0f - alpha));
        }
        toff += (1 << d);
        uoff += nout;
    }
    __shared__ float red[256];
    red[threadIdx.x] = local;
    __syncthreads();
    for (int s = 128; s > 0; s >>= 1) {
        if (threadIdx.x < s) red[threadIdx.x] += red[threadIdx.x + s];
        __syncthreads();
    }
    if (threadIdx.x == 0) out[0] = red[0];
}

// ---------------- launch ----------------
extern "C" void kernel_launch(void* const* d_in, const int* in_sizes, int n_in,
                              void* d_out, int out_size) {
    const float* X  = (const float*)d_in[0];   // [16384, 1024]
    const float* Wi = (const float*)d_in[1];   // [1023, 1025]
    const float* Wl = (const float*)d_in[2];   // [1000, 1024]
    float* out = (float*)d_out;

    __nv_bfloat16 *xhi, *xlo, *phip, *plop, *whi, *wlo, *lhi, *llo;
    float *s_p, *bias_p, *t_p, *u_p;
    cudaGetSymbolAddress((void**)&xhi,  g_Xhi);
    cudaGetSymbolAddress((void**)&xlo,  g_Xlo);
    cudaGetSymbolAddress((void**)&phip, g_Phi);
    cudaGetSymbolAddress((void**)&plop, g_Plo);
    cudaGetSymbolAddress((void**)&whi,  g_Whi);
    cudaGetSymbolAddress((void**)&wlo,  g_Wlo);
    cudaGetSymbolAddress((void**)&lhi,  g_Lhi);
    cudaGetSymbolAddress((void**)&llo,  g_Llo);
    cudaGetSymbolAddress((void**)&s_p,  g_s);
    cudaGetSymbolAddress((void**)&bias_p, g_bias);
    cudaGetSymbolAddress((void**)&t_p,  g_T);
    cudaGetSymbolAddress((void**)&u_p,  g_U);

    cudaFuncSetAttribute(mma_gemm_kernel<true>,
                         cudaFuncAttributeMaxDynamicSharedMemorySize, DYN_SMEM);
    cudaFuncSetAttribute(mma_gemm_kernel<false>,
                         cudaFuncAttributeMaxDynamicSharedMemorySize, DYN_SMEM);

    // 1. split inputs into bf16 hi/lo
    split_x_kernel<<<(B_SZ * KDIM / 4 + 255) / 256, 256>>>(X, xhi, xlo);
    repack_w_kernel<<<(KDIM * KDIM + 255) / 256, 256>>>(Wi, whi, wlo, bias_p);
    repack_l_kernel<<<(KDIM * KDIM + 255) / 256, 256>>>(Wl, lhi, llo);
    zero_kernel<<<8, 256>>>(t_p, u_p);

    // 2. GEMM1 + bias + sigmoid -> g_s (fp32, ld=1024)
    {
        dim3 grid(8, B_SZ / 128);
        mma_gemm_kernel<true><<<grid, 256, DYN_SMEM>>>(
            xhi, xlo, whi, wlo, bias_p, s_p, 1024, 1024);
    }

    // 3. path probs (bf16 hi/lo) + regularizer partial sums
    path_kernel<<<B_SZ / SAMPLES_PER_BLOCK, 256>>>(s_p, phip, plop, t_p, u_p);

    // 4. GEMM2: predictions = path @ W_leaf^T -> d_out (ld=1000, clip 1000)
    {
        dim3 grid(8, B_SZ / 128);
        mma_gemm_kernel<false><<<grid, 256, DYN_SMEM>>>(
            phip, plop, lhi, llo, nullptr, out, OUT_DIM, OUT_DIM);
    }

    // 5. regularizer scalar -> last output element
    reg_kernel<<<1, 256>>>(t_p, u_p, out + (out_size - 1));
}

// round 5
// speedup vs baseline: 2.7394x; 1.0036x over previous
#include <cuda_runtime.h>
#include <cuda_bf16.h>
#include <cstdint>
#include <math.h>

// ---------------- problem constants ----------------
#define B_SZ      16384
#define KDIM      1024
#define OUT_DIM   1000
#define N_INT     1023
#define DEPTH     10
#define LAMBDA    1e-3f

// ---------------- scratch (device globals) ----------------
__device__ __nv_bfloat16 g_Xhi[(size_t)B_SZ * KDIM];
__device__ __nv_bfloat16 g_Xlo[(size_t)B_SZ * KDIM];
__device__ __nv_bfloat16 g_Phi[(size_t)B_SZ * KDIM];
__device__ __nv_bfloat16 g_Plo[(size_t)B_SZ * KDIM];
__device__ __nv_bfloat16 g_Whi[(size_t)KDIM * KDIM];
__device__ __nv_bfloat16 g_Wlo[(size_t)KDIM * KDIM];
__device__ __nv_bfloat16 g_Lhi[(size_t)KDIM * KDIM];
__device__ __nv_bfloat16 g_Llo[(size_t)KDIM * KDIM];
__device__ float g_s[(size_t)B_SZ * KDIM];
__device__ float g_bias[KDIM];
__device__ float g_T[1023];
__device__ float g_U[2046];

// ---------------- PTX helpers (sm_80-class features only) ----------------
__device__ __forceinline__ uint32_t smem_u32(const void* p) {
    uint32_t a;
    asm("{ .reg .u64 t; cvta.to.shared.u64 t, %1; cvt.u32.u64 %0, t; }" : "=r"(a) : "l"(p));
    return a;
}

#define CP_ASYNC16(dst, src) \
    asm volatile("cp.async.cg.shared.global [%0], [%1], 16;" :: "r"(dst), "l"(src))
#define CP_COMMIT() asm volatile("cp.async.commit_group;" ::: "memory")
#define CP_WAIT(n)  asm volatile("cp.async.wait_group %0;" :: "n"(n) : "memory")

#define LDMX4(r0, r1, r2, r3, addr) \
    asm volatile("ldmatrix.sync.aligned.m8n8.x4.shared.b16 {%0,%1,%2,%3}, [%4];" \
        : "=r"(r0), "=r"(r1), "=r"(r2), "=r"(r3) : "r"(addr))

#define MMA16816(d, a, b) \
    asm volatile("mma.sync.aligned.m16n8k16.row.col.f32.bf16.bf16.f32 " \
        "{%0,%1,%2,%3}, {%4,%5,%6,%7}, {%8,%9}, {%0,%1,%2,%3};" \
        : "+f"((d)[0]), "+f"((d)[1]), "+f"((d)[2]), "+f"((d)[3]) \
        : "r"((a)[0]), "r"((a)[1]), "r"((a)[2]), "r"((a)[3]), \
          "r"((b)[0]), "r"((b)[1]))

// ---------------- fp32 -> bf16 hi/lo split ----------------
__device__ __forceinline__ void split2(float x, __nv_bfloat16& h, __nv_bfloat16& l) {
    h = __float2bfloat16(x);
    l = __float2bfloat16(x - __bfloat162float(h));
}

__global__ void split_x_kernel(const float* __restrict__ src,
                               __nv_bfloat16* __restrict__ hi,
                               __nv_bfloat16* __restrict__ lo) {
    size_t i = (size_t)blockIdx.x * blockDim.x + threadIdx.x;  // quad index
    float4 v = ((const float4*)src)[i];
    __nv_bfloat16 h0, h1, h2, h3, l0, l1, l2, l3;
    split2(v.x, h0, l0); split2(v.y, h1, l1); split2(v.z, h2, l2); split2(v.w, h3, l3);
    ((__nv_bfloat162*)hi)[2 * i]     = __nv_bfloat162(h0, h1);
    ((__nv_bfloat162*)hi)[2 * i + 1] = __nv_bfloat162(h2, h3);
    ((__nv_bfloat162*)lo)[2 * i]     = __nv_bfloat162(l0, l1);
    ((__nv_bfloat162*)lo)[2 * i + 1] = __nv_bfloat162(l2, l3);
}

// also zeroes the T/U accumulators (folded former zero_kernel)
__global__ void repack_w_kernel(const float* __restrict__ Wi,
                                __nv_bfloat16* __restrict__ hi,
                                __nv_bfloat16* __restrict__ lo,
                                float* __restrict__ bias,
                                float* __restrict__ t, float* __restrict__ u) {
    int idx = blockIdx.x * blockDim.x + threadIdx.x;
    if (idx < KDIM * KDIM) {
        int n = idx >> 10, k = idx & 1023;
        float v = (n < N_INT) ? Wi[(size_t)n * 1025 + 1 + k] : 0.0f;
        __nv_bfloat16 h, l; split2(v, h, l);
        hi[idx] = h; lo[idx] = l;
    }
    if (idx < KDIM) bias[idx] = (idx < N_INT) ? Wi[(size_t)idx * 1025] : 0.0f;
    if (idx < 1023) t[idx] = 0.0f;
    if (idx < 2046) u[idx] = 0.0f;
}

__global__ void repack_l_kernel(const float* __restrict__ Wl,
                                __nv_bfloat16* __restrict__ hi,
                                __nv_bfloat16* __restrict__ lo) {
    int idx = blockIdx.x * blockDim.x + threadIdx.x;
    if (idx < KDIM * KDIM) {
        int n = idx >> 10, k = idx & 1023;
        float v = (n < OUT_DIM) ? Wl[(size_t)n * KDIM + k] : 0.0f;
        __nv_bfloat16 h, l; split2(v, h, l);
        hi[idx] = h; lo[idx] = l;
    }
}

// ---------------- mma.sync GEMM: C[M,N] = A * B^T (3-term bf16 emulation) ---
// CTA tile 256x128, BK=32, 3-stage cp.async pipeline, 256 threads (8 warps
// in 4Mx2N), warp tile 64x64 via m16n8k16.
#define ROWB        80                    // 64B data + 16B pad (conflict-free)
#define A_ROWS      256
#define B_ROWS      128
#define OFF_AHI     0
#define OFF_ALO     (A_ROWS * ROWB)                    // 20480
#define OFF_BHI     (2 * A_ROWS * ROWB)                // 40960
#define OFF_BLO     (2 * A_ROWS * ROWB + B_ROWS * ROWB)// 51200
#define STAGE_BYTES ((2 * A_ROWS + 2 * B_ROWS) * ROWB) // 61440
#define NCHUNK      32                    // K=1024 / BK=32
#define DYN_SMEM    (3 * STAGE_BYTES + 512)

__device__ __forceinline__ void load_stage(
        const __nv_bfloat16* __restrict__ Ahi, const __nv_bfloat16* __restrict__ Alo,
        const __nv_bfloat16* __restrict__ Bhi, const __nv_bfloat16* __restrict__ Blo,
        int m0, int n0, int chunk, uint32_t sb, int tid) {
    const int r = tid >> 2;            // 0..63
    const int c = tid & 3;
    const int kk = chunk * 32 + c * 8;
    const uint32_t doff = (uint32_t)r * ROWB + (uint32_t)c * 16;
#pragma unroll
    for (int h = 0; h < 4; h++) {      // A: 256 rows
        const int rr = r + h * 64;
        const uint32_t d = sb + doff + (uint32_t)(h * 64 * ROWB);
        CP_ASYNC16(d + OFF_AHI, Ahi + (size_t)(m0 + rr) * KDIM + kk);
        CP_ASYNC16(d + OFF_ALO, Alo + (size_t)(m0 + rr) * KDIM + kk);
    }
#pragma unroll
    for (int h = 0; h < 2; h++) {      // B: 128 rows
        const int rr = r + h * 64;
        const uint32_t d = sb + doff + (uint32_t)(h * 64 * ROWB);
        CP_ASYNC16(d + OFF_BHI, Bhi + (size_t)(n0 + rr) * KDIM + kk);
        CP_ASYNC16(d + OFF_BLO, Blo + (size_t)(n0 + rr) * KDIM + kk);
    }
}

template<bool SIG>
__global__ void __launch_bounds__(256, 1)
mma_gemm_kernel(const __nv_bfloat16* __restrict__ Ahi, const __nv_bfloat16* __restrict__ Alo,
                const __nv_bfloat16* __restrict__ Bhi, const __nv_bfloat16* __restrict__ Blo,
                const float* __restrict__ bias, float* __restrict__ C,
                int ldc, int nclip) {
    extern __shared__ char sm[];
    const uint32_t s0 = smem_u32(sm);
    float* bias_sh = (float*)(sm + 3 * STAGE_BYTES);

    const int tid  = threadIdx.x;
    const int lane = tid & 31;
    const int wid  = tid >> 5;
    const int wm   = wid & 3;    // 4 M-warps of 64 rows
    const int wn   = wid >> 2;   // 2 N-warps of 64 cols
    const int m0   = blockIdx.y * 256;
    const int n0   = blockIdx.x * 128;

    if (SIG && tid < 128) bias_sh[tid] = bias[n0 + tid];

    float acc[4][8][4];
#pragma unroll
    for (int mi = 0; mi < 4; mi++)
#pragma unroll
        for (int ni = 0; ni < 8; ni++)
#pragma unroll
            for (int j = 0; j < 4; j++) acc[mi][ni][j] = 0.0f;

    // ldmatrix per-thread address components
    const uint32_t a_off = (uint32_t)(wm * 64 + (lane & 15)) * ROWB
                         + (uint32_t)(lane >> 4) * 16;
    const uint32_t b_off = (uint32_t)(wn * 64 + ((lane >> 4) & 1) * 8 + (lane & 7)) * ROWB
                         + (uint32_t)((lane >> 3) & 1) * 16;

    load_stage(Ahi, Alo, Bhi, Blo, m0, n0, 0, s0, tid);               CP_COMMIT();
    load_stage(Ahi, Alo, Bhi, Blo, m0, n0, 1, s0 + STAGE_BYTES, tid); CP_COMMIT();

    for (int cch = 0; cch < NCHUNK; cch++) {
        if (cch + 2 < NCHUNK) {
            load_stage(Ahi, Alo, Bhi, Blo, m0, n0, cch + 2,
                       s0 + (uint32_t)((cch + 2) % 3) * STAGE_BYTES, tid);
            CP_COMMIT();
            CP_WAIT(2);
        } else if (cch + 1 < NCHUNK) {
            CP_WAIT(1);
        } else {
            CP_WAIT(0);
        }
        __syncthreads();

        const uint32_t sb = s0 + (uint32_t)(cch % 3) * STAGE_BYTES;
#pragma unroll
        for (int ks = 0; ks < 2; ks++) {
            uint32_t ah[4][4], al[4][4];
#pragma unroll
            for (int mi = 0; mi < 4; mi++) {
                const uint32_t ao = sb + a_off + (uint32_t)(mi * 16 * ROWB) + (uint32_t)(ks * 32);
                LDMX4(ah[mi][0], ah[mi][1], ah[mi][2], ah[mi][3], ao + OFF_AHI);
                LDMX4(al[mi][0], al[mi][1], al[mi][2], al[mi][3], ao + OFF_ALO);
            }
            // two half-passes over N to cap live B registers
#pragma unroll
            for (int half = 0; half < 2; half++) {
                uint32_t bh[4][2], bl[4][2];
#pragma unroll
                for (int p = 0; p < 2; p++) {
                    const int pj = half * 2 + p;
                    const uint32_t bo = sb + b_off + (uint32_t)(pj * 16 * ROWB)
                                      + (uint32_t)(ks * 32);
                    LDMX4(bh[2 * p][0], bh[2 * p][1], bh[2 * p + 1][0], bh[2 * p + 1][1],
                          bo + OFF_BHI);
                    LDMX4(bl[2 * p][0], bl[2 * p][1], bl[2 * p + 1][0], bl[2 * p + 1][1],
                          bo + OFF_BLO);
                }
#pragma unroll
                for (int mi = 0; mi < 4; mi++)
#pragma unroll
                    for (int nj = 0; nj < 4; nj++) {
                        float* a4 = acc[mi][half * 4 + nj];
                        MMA16816(a4, ah[mi], bh[nj]);
                        MMA16816(a4, ah[mi], bl[nj]);
                        MMA16816(a4, al[mi], bh[nj]);
                    }
            }
        }
        __syncthreads();
    }

    // epilogue: direct register -> global stores (float2, 8B aligned)
    const int tr = lane >> 2;
    const int tc = (lane & 3) * 2;
#pragma unroll
    for (int mi = 0; mi < 4; mi++) {
#pragma unroll
        for (int ni = 0; ni < 8; ni++) {
            const int row = m0 + wm * 64 + mi * 16 + tr;
            const int col = n0 + wn * 64 + ni * 8 + tc;
            float v0 = acc[mi][ni][0], v1 = acc[mi][ni][1];
            float v2 = acc[mi][ni][2], v3 = acc[mi][ni][3];
            if (SIG) {
                const float b0 = bias_sh[col - n0];
                const float b1 = bias_sh[col - n0 + 1];
                v0 = 1.0f / (1.0f + expf(-(v0 + b0)));
                v1 = 1.0f / (1.0f + expf(-(v1 + b1)));
                v2 = 1.0f / (1.0f + expf(-(v2 + b0)));
                v3 = 1.0f / (1.0f + expf(-(v3 + b1)));
            }
            if (col < nclip) {  // col even, nclip even -> pair never straddles
                *(float2*)&C[(size_t)row * ldc + col]       = make_float2(v0, v1);
                *(float2*)&C[(size_t)(row + 8) * ldc + col] = make_float2(v2, v3);
            }
        }
    }
}

// ---------------- path + regularizer partial sums ----------------
#define SAMPLES_PER_BLOCK 16

__global__ void __launch_bounds__(256)
path_kernel(const float* __restrict__ s_g,
            __nv_bfloat16* __restrict__ phi, __nv_bfloat16* __restrict__ plo,
            float* __restrict__ gT, float* __restrict__ gU) {
    __shared__ float s_sh[1024];
    __shared__ float bufA[1024];
    __shared__ float bufB[1024];
    __shared__ float Tacc[1023];
    __shared__ float Uacc[2046];

    const int tid = threadIdx.x;
    for (int i = tid; i < 1023; i += 256) Tacc[i] = 0.0f;
    for (int i = tid; i < 2046; i += 256) Uacc[i] = 0.0f;

    const int base = blockIdx.x * SAMPLES_PER_BLOCK;

    for (int s = 0; s < SAMPLES_PER_BLOCK; s++) {
        const int b = base + s;
        __syncthreads();
        for (int i = tid; i < 1024; i += 256)
            s_sh[i] = s_g[(size_t)b * 1024 + i];
        if (tid == 0) bufA[0] = 1.0f;
        __syncthreads();

        float* cur = bufA;
        float* nxt = bufB;
        int toff = 0, uoff = 0;

#pragma unroll
        for (int d = 0; d < DEPTH; d++) {
            const int nout = 2 << d;
            const int nbase = (1 << d) - 1;
            for (int k = tid; k < nout; k += 256) {
                float sv = s_sh[nbase + (k >> 1)];
                float lp = (k & 1) ? (1.0f - sv) : sv;
                float nk = cur[k >> 1] * lp;
                nxt[k] = nk;
                // parent-in-new path prob, recomputed locally (no extra barrier)
                int p = k >> 1;
                float svp = s_sh[nbase + (p >> 1)];
                float lpp = (p & 1) ? (1.0f - svp) : svp;
                float pn = cur[p >> 1] * lpp;
                Uacc[uoff + k] += lp * pn;
                if (k < (nout >> 1)) Tacc[toff + k] += nk;
            }
            __syncthreads();
            toff += nout >> 1;
            uoff += nout;
            float* t = cur; cur = nxt; nxt = t;
        }

        for (int l = tid; l < 1024; l += 256) {
            float p = cur[l];
            __nv_bfloat16 h, lo; split2(p, h, lo);
            phi[(size_t)b * 1024 + l] = h;
            plo[(size_t)b * 1024 + l] = lo;
        }
    }

    __syncthreads();
    for (int i = tid; i < 1023; i += 256) atomicAdd(&gT[i], Tacc[i]);
    for (int i = tid; i < 2046; i += 256) atomicAdd(&gU[i], Uacc[i]);
}

// ---------------- regularizer scalar ----------------
__global__ void reg_kernel(const float* __restrict__ gT, const float* __restrict__ gU,
                           float* __restrict__ out) {
    float local = 0.0f;
    int toff = 0, uoff = 0;
#pragma unroll
    for (int d = 0; d < DEPTH; d++) {
        const int nout = 2 << d;
        const float factor = LAMBDA * exp2f(-(float)d);
        for (int k = threadIdx.x; k < nout; k += 256) {
            float den = gT[toff + (k >> 1)] + 1e-8f;
            float alpha = gU[uoff + k] / den;
            local += factor * (-0.5f) * (logf(alpha) + logf(1.0f - alpha));
        }
        toff += (1 << d);
        uoff += nout;
    }
    __shared__ float red[256];
    red[threadIdx.x] = local;
    __syncthreads();
    for (int s = 128; s > 0; s >>= 1) {
        if (threadIdx.x < s) red[threadIdx.x] += red[threadIdx.x + s];
        __syncthreads();
    }
    if (threadIdx.x == 0) out[0] = red[0];
}

// ---------------- launch ----------------
extern "C" void kernel_launch(void* const* d_in, const int* in_sizes, int n_in,
                              void* d_out, int out_size) {
    const float* X  = (const float*)d_in[0];   // [16384, 1024]
    const float* Wi = (const float*)d_in[1];   // [1023, 1025]
    const float* Wl = (const float*)d_in[2];   // [1000, 1024]
    float* out = (float*)d_out;

    __nv_bfloat16 *xhi, *xlo, *phip, *plop, *whi, *wlo, *lhi, *llo;
    float *s_p, *bias_p, *t_p, *u_p;
    cudaGetSymbolAddress((void**)&xhi,  g_Xhi);
    cudaGetSymbolAddress((void**)&xlo,  g_Xlo);
    cudaGetSymbolAddress((void**)&phip, g_Phi);
    cudaGetSymbolAddress((void**)&plop, g_Plo);
    cudaGetSymbolAddress((void**)&whi,  g_Whi);
    cudaGetSymbolAddress((void**)&wlo,  g_Wlo);
    cudaGetSymbolAddress((void**)&lhi,  g_Lhi);
    cudaGetSymbolAddress((void**)&llo,  g_Llo);
    cudaGetSymbolAddress((void**)&s_p,  g_s);
    cudaGetSymbolAddress((void**)&bias_p, g_bias);
    cudaGetSymbolAddress((void**)&t_p,  g_T);
    cudaGetSymbolAddress((void**)&u_p,  g_U);

    cudaFuncSetAttribute(mma_gemm_kernel<true>,
                         cudaFuncAttributeMaxDynamicSharedMemorySize, DYN_SMEM);
    cudaFuncSetAttribute(mma_gemm_kernel<false>,
                         cudaFuncAttributeMaxDynamicSharedMemorySize, DYN_SMEM);

    // 1. split inputs into bf16 hi/lo (+ zero T/U inside repack_w)
    split_x_kernel<<<(B_SZ * KDIM / 4 + 255) / 256, 256>>>(X, xhi, xlo);
    repack_w_kernel<<<(KDIM * KDIM + 255) / 256, 256>>>(Wi, whi, wlo, bias_p, t_p, u_p);
    repack_l_kernel<<<(KDIM * KDIM + 255) / 256, 256>>>(Wl, lhi, llo);

    // 2. GEMM1 + bias + sigmoid -> g_s (fp32, ld=1024)
    {
        dim3 grid(8, B_SZ / 256);   // (8, 64)
        mma_gemm_kernel<true><<<grid, 256, DYN_SMEM>>>(
            xhi, xlo, whi, wlo, bias_p, s_p, 1024, 1024);
    }

    // 3. path probs (bf16 hi/lo) + regularizer partial sums
    path_kernel<<<B_SZ / SAMPLES_PER_BLOCK, 256>>>(s_p, phip, plop, t_p, u_p);

    // 4. GEMM2: predictions = path @ W_leaf^T -> d_out (ld=1000, clip 1000)
    {
        dim3 grid(8, B_SZ / 256);
        mma_gemm_kernel<false><<<grid, 256, DYN_SMEM>>>(
            phip, plop, lhi, llo, nullptr, out, OUT_DIM, OUT_DIM);
    }

    // 5. regularizer scalar -> last output element
    reg_kernel<<<1, 256>>>(t_p, u_p, out + (out_size - 1));
}

// round 6
// speedup vs baseline: 2.8466x; 1.0391x over previous
#include <cuda_runtime.h>
#include <cuda_bf16.h>
#include <cstdint>
#include <math.h>

// ---------------- problem constants ----------------
#define B_SZ      16384
#define KDIM      1024
#define OUT_DIM   1000
#define N_INT     1023
#define DEPTH     10
#define LAMBDA    1e-3f

// ---------------- scratch (device globals) ----------------
__device__ __nv_bfloat16 g_Xhi[(size_t)B_SZ * KDIM];
__device__ __nv_bfloat16 g_Xlo[(size_t)B_SZ * KDIM];
__device__ __nv_bfloat16 g_Phi[(size_t)B_SZ * KDIM];
__device__ __nv_bfloat16 g_Plo[(size_t)B_SZ * KDIM];
__device__ __nv_bfloat16 g_Whi[(size_t)KDIM * KDIM];
__device__ __nv_bfloat16 g_Wlo[(size_t)KDIM * KDIM];
__device__ __nv_bfloat16 g_Lhi[(size_t)KDIM * KDIM];
__device__ __nv_bfloat16 g_Llo[(size_t)KDIM * KDIM];
__device__ float g_s[(size_t)B_SZ * KDIM];
__device__ float g_bias[KDIM];
__device__ float g_T[1023];
__device__ float g_U[2046];

// ---------------- PTX helpers (sm_80-class features only) ----------------
__device__ __forceinline__ uint32_t smem_u32(const void* p) {
    uint32_t a;
    asm("{ .reg .u64 t; cvta.to.shared.u64 t, %1; cvt.u32.u64 %0, t; }" : "=r"(a) : "l"(p));
    return a;
}

#define CP_ASYNC16(dst, src) \
    asm volatile("cp.async.cg.shared.global [%0], [%1], 16;" :: "r"(dst), "l"(src))
#define CP_COMMIT() asm volatile("cp.async.commit_group;" ::: "memory")
#define CP_WAIT(n)  asm volatile("cp.async.wait_group %0;" :: "n"(n) : "memory")

#define LDMX4(r0, r1, r2, r3, addr) \
    asm volatile("ldmatrix.sync.aligned.m8n8.x4.shared.b16 {%0,%1,%2,%3}, [%4];" \
        : "=r"(r0), "=r"(r1), "=r"(r2), "=r"(r3) : "r"(addr))

#define MMA16816(d, a, b) \
    asm volatile("mma.sync.aligned.m16n8k16.row.col.f32.bf16.bf16.f32 " \
        "{%0,%1,%2,%3}, {%4,%5,%6,%7}, {%8,%9}, {%0,%1,%2,%3};" \
        : "+f"((d)[0]), "+f"((d)[1]), "+f"((d)[2]), "+f"((d)[3]) \
        : "r"((a)[0]), "r"((a)[1]), "r"((a)[2]), "r"((a)[3]), \
          "r"((b)[0]), "r"((b)[1]))

// ---------------- fp32 -> bf16 hi/lo split ----------------
__device__ __forceinline__ void split2(float x, __nv_bfloat16& h, __nv_bfloat16& l) {
    h = __float2bfloat16(x);
    l = __float2bfloat16(x - __bfloat162float(h));
}

__global__ void split_x_kernel(const float* __restrict__ src,
                               __nv_bfloat16* __restrict__ hi,
                               __nv_bfloat16* __restrict__ lo) {
    size_t i = (size_t)blockIdx.x * blockDim.x + threadIdx.x;  // quad index
    float4 v = ((const float4*)src)[i];
    __nv_bfloat16 h0, h1, h2, h3, l0, l1, l2, l3;
    split2(v.x, h0, l0); split2(v.y, h1, l1); split2(v.z, h2, l2); split2(v.w, h3, l3);
    ((__nv_bfloat162*)hi)[2 * i]     = __nv_bfloat162(h0, h1);
    ((__nv_bfloat162*)hi)[2 * i + 1] = __nv_bfloat162(h2, h3);
    ((__nv_bfloat162*)lo)[2 * i]     = __nv_bfloat162(l0, l1);
    ((__nv_bfloat162*)lo)[2 * i + 1] = __nv_bfloat162(l2, l3);
}

// also zeroes the T/U accumulators
__global__ void repack_w_kernel(const float* __restrict__ Wi,
                                __nv_bfloat16* __restrict__ hi,
                                __nv_bfloat16* __restrict__ lo,
                                float* __restrict__ bias,
                                float* __restrict__ t, float* __restrict__ u) {
    int idx = blockIdx.x * blockDim.x + threadIdx.x;
    if (idx < KDIM * KDIM) {
        int n = idx >> 10, k = idx & 1023;
        float v = (n < N_INT) ? Wi[(size_t)n * 1025 + 1 + k] : 0.0f;
        __nv_bfloat16 h, l; split2(v, h, l);
        hi[idx] = h; lo[idx] = l;
    }
    if (idx < KDIM) bias[idx] = (idx < N_INT) ? Wi[(size_t)idx * 1025] : 0.0f;
    if (idx < 1023) t[idx] = 0.0f;
    if (idx < 2046) u[idx] = 0.0f;
}

__global__ void repack_l_kernel(const float* __restrict__ Wl,
                                __nv_bfloat16* __restrict__ hi,
                                __nv_bfloat16* __restrict__ lo) {
    int idx = blockIdx.x * blockDim.x + threadIdx.x;
    if (idx < KDIM * KDIM) {
        int n = idx >> 10, k = idx & 1023;
        float v = (n < OUT_DIM) ? Wl[(size_t)n * KDIM + k] : 0.0f;
        __nv_bfloat16 h, l; split2(v, h, l);
        hi[idx] = h; lo[idx] = l;
    }
}

// ---------------- mma.sync GEMM: C[M,N] = A * B^T (3-term bf16 emulation) ---
// CTA tile 128x128, BK=16, 4-stage cp.async ring, 256 threads (8 warps 4Mx2N,
// warp tile 32x64), 2 CTAs/SM. One __syncthreads per K-chunk.
#define ROWB        48                    // 32B data + 16B pad (conflict-free)
#define TROWS       128
#define OFF_AHI     0
#define OFF_ALO     (TROWS * ROWB)        // 6144
#define OFF_BHI     (2 * TROWS * ROWB)    // 12288
#define OFF_BLO     (3 * TROWS * ROWB)    // 18432
#define STAGE_BYTES (4 * TROWS * ROWB)    // 24576
#define NSTAGE      4
#define NCHUNK      64                    // K=1024 / BK=16
#define DYN_SMEM    (NSTAGE * STAGE_BYTES + 512)

__device__ __forceinline__ void load_stage(
        const __nv_bfloat16* __restrict__ Ahi, const __nv_bfloat16* __restrict__ Alo,
        const __nv_bfloat16* __restrict__ Bhi, const __nv_bfloat16* __restrict__ Blo,
        int m0, int n0, int chunk, uint32_t sb, int tid) {
    const int r = tid >> 1;            // 0..127
    const int c = tid & 1;             // which 16B half of the 32B row
    const int kk = chunk * 16 + c * 8; // bf16 element offset
    const uint32_t d = sb + (uint32_t)r * ROWB + (uint32_t)c * 16;
    CP_ASYNC16(d + OFF_AHI, Ahi + (size_t)(m0 + r) * KDIM + kk);
    CP_ASYNC16(d + OFF_ALO, Alo + (size_t)(m0 + r) * KDIM + kk);
    CP_ASYNC16(d + OFF_BHI, Bhi + (size_t)(n0 + r) * KDIM + kk);
    CP_ASYNC16(d + OFF_BLO, Blo + (size_t)(n0 + r) * KDIM + kk);
}

template<bool SIG>
__global__ void __launch_bounds__(256, 2)
mma_gemm_kernel(const __nv_bfloat16* __restrict__ Ahi, const __nv_bfloat16* __restrict__ Alo,
                const __nv_bfloat16* __restrict__ Bhi, const __nv_bfloat16* __restrict__ Blo,
                const float* __restrict__ bias, float* __restrict__ C,
                int ldc, int nclip) {
    extern __shared__ char sm[];
    const uint32_t s0 = smem_u32(sm);
    float* bias_sh = (float*)(sm + NSTAGE * STAGE_BYTES);

    const int tid  = threadIdx.x;
    const int lane = tid & 31;
    const int wid  = tid >> 5;
    const int wm   = wid & 3;    // 4 M-warps of 32 rows
    const int wn   = wid >> 2;   // 2 N-warps of 64 cols
    const int m0   = blockIdx.y * 128;
    const int n0   = blockIdx.x * 128;

    if (SIG && tid < 128) bias_sh[tid] = bias[n0 + tid];

    float acc[2][8][4];
#pragma unroll
    for (int mi = 0; mi < 2; mi++)
#pragma unroll
        for (int ni = 0; ni < 8; ni++)
#pragma unroll
            for (int j = 0; j < 4; j++) acc[mi][ni][j] = 0.0f;

    // ldmatrix per-thread address components (k16 = full 32B row)
    const uint32_t a_off = (uint32_t)(wm * 32 + (lane & 15)) * ROWB
                         + (uint32_t)(lane >> 4) * 16;
    const uint32_t b_off = (uint32_t)(wn * 64 + ((lane >> 4) & 1) * 8 + (lane & 7)) * ROWB
                         + (uint32_t)((lane >> 3) & 1) * 16;

    // prologue: stages 0..2
    load_stage(Ahi, Alo, Bhi, Blo, m0, n0, 0, s0, tid);                   CP_COMMIT();
    load_stage(Ahi, Alo, Bhi, Blo, m0, n0, 1, s0 + STAGE_BYTES, tid);     CP_COMMIT();
    load_stage(Ahi, Alo, Bhi, Blo, m0, n0, 2, s0 + 2 * STAGE_BYTES, tid); CP_COMMIT();

    for (int s = 0; s < NCHUNK; s++) {
        if (s <= NCHUNK - 3)      CP_WAIT(2);   // stage s arrived (this thread)
        else if (s == NCHUNK - 2) CP_WAIT(1);
        else                      CP_WAIT(0);
        __syncthreads();                        // everyone's stage-s data + stage s-1 consumed

        if (s + 3 < NCHUNK) {                   // prefetch stage s+3 (overwrites s-1)
            load_stage(Ahi, Alo, Bhi, Blo, m0, n0, s + 3,
                       s0 + (uint32_t)((s + 3) & 3) * STAGE_BYTES, tid);
            CP_COMMIT();
        }

        const uint32_t sb = s0 + (uint32_t)(s & 3) * STAGE_BYTES;
        uint32_t ah[2][4], al[2][4];
#pragma unroll
        for (int mi = 0; mi < 2; mi++) {
            const uint32_t ao = sb + a_off + (uint32_t)(mi * 16 * ROWB);
            LDMX4(ah[mi][0], ah[mi][1], ah[mi][2], ah[mi][3], ao + OFF_AHI);
            LDMX4(al[mi][0], al[mi][1], al[mi][2], al[mi][3], ao + OFF_ALO);
        }
#pragma unroll
        for (int half = 0; half < 2; half++) {
            uint32_t bh[4][2], bl[4][2];
#pragma unroll
            for (int p = 0; p < 2; p++) {
                const int pj = half * 2 + p;
                const uint32_t bo = sb + b_off + (uint32_t)(pj * 16 * ROWB);
                LDMX4(bh[2 * p][0], bh[2 * p][1], bh[2 * p + 1][0], bh[2 * p + 1][1],
                      bo + OFF_BHI);
                LDMX4(bl[2 * p][0], bl[2 * p][1], bl[2 * p + 1][0], bl[2 * p + 1][1],
                      bo + OFF_BLO);
            }
#pragma unroll
            for (int mi = 0; mi < 2; mi++)
#pragma unroll
                for (int nj = 0; nj < 4; nj++) {
                    float* a4 = acc[mi][half * 4 + nj];
                    MMA16816(a4, ah[mi], bh[nj]);
                    MMA16816(a4, ah[mi], bl[nj]);
                    MMA16816(a4, al[mi], bh[nj]);
                }
        }
    }

    // epilogue: direct register -> global stores (float2, 8B aligned)
    const int tr = lane >> 2;
    const int tc = (lane & 3) * 2;
#pragma unroll
    for (int mi = 0; mi < 2; mi++) {
#pragma unroll
        for (int ni = 0; ni < 8; ni++) {
            const int row = m0 + wm * 32 + mi * 16 + tr;
            const int col = n0 + wn * 64 + ni * 8 + tc;
            float v0 = acc[mi][ni][0], v1 = acc[mi][ni][1];
            float v2 = acc[mi][ni][2], v3 = acc[mi][ni][3];
            if (SIG) {
                const float b0 = bias_sh[col - n0];
                const float b1 = bias_sh[col - n0 + 1];
                v0 = 1.0f / (1.0f + expf(-(v0 + b0)));
                v1 = 1.0f / (1.0f + expf(-(v1 + b1)));
                v2 = 1.0f / (1.0f + expf(-(v2 + b0)));
                v3 = 1.0f / (1.0f + expf(-(v3 + b1)));
            }
            if (col < nclip) {  // col even, nclip even -> pair never straddles
                *(float2*)&C[(size_t)row * ldc + col]       = make_float2(v0, v1);
                *(float2*)&C[(size_t)(row + 8) * ldc + col] = make_float2(v2, v3);
            }
        }
    }
}

// ---------------- path + regularizer partial sums ----------------
#define SAMPLES_PER_BLOCK 16

__global__ void __launch_bounds__(256)
path_kernel(const float* __restrict__ s_g,
            __nv_bfloat16* __restrict__ phi, __nv_bfloat16* __restrict__ plo,
            float* __restrict__ gT, float* __restrict__ gU) {
    __shared__ float s_sh[1024];
    __shared__ float bufA[1024];
    __shared__ float bufB[1024];
    __shared__ float Tacc[1023];
    __shared__ float Uacc[2046];

    const int tid = threadIdx.x;
    for (int i = tid; i < 1023; i += 256) Tacc[i] = 0.0f;
    for (int i = tid; i < 2046; i += 256) Uacc[i] = 0.0f;

    const int base = blockIdx.x * SAMPLES_PER_BLOCK;

    for (int s = 0; s < SAMPLES_PER_BLOCK; s++) {
        const int b = base + s;
        __syncthreads();
        for (int i = tid; i < 1024; i += 256)
            s_sh[i] = s_g[(size_t)b * 1024 + i];
        if (tid == 0) bufA[0] = 1.0f;
        __syncthreads();

        float* cur = bufA;
        float* nxt = bufB;
        int toff = 0, uoff = 0;

#pragma unroll
        for (int d = 0; d < DEPTH; d++) {
            const int nout = 2 << d;
            const int nbase = (1 << d) - 1;
            for (int k = tid; k < nout; k += 256) {
                float sv = s_sh[nbase + (k >> 1)];
                float lp = (k & 1) ? (1.0f - sv) : sv;
                float nk = cur[k >> 1] * lp;
                nxt[k] = nk;
                int p = k >> 1;
                float svp = s_sh[nbase + (p >> 1)];
                float lpp = (p & 1) ? (1.0f - svp) : svp;
                float pn = cur[p >> 1] * lpp;
                Uacc[uoff + k] += lp * pn;
                if (k < (nout >> 1)) Tacc[toff + k] += nk;
            }
            __syncthreads();
            toff += nout >> 1;
            uoff += nout;
            float* t = cur; cur = nxt; nxt = t;
        }

        for (int l = tid; l < 1024; l += 256) {
            float p = cur[l];
            __nv_bfloat16 h, lo; split2(p, h, lo);
            phi[(size_t)b * 1024 + l] = h;
            plo[(size_t)b * 1024 + l] = lo;
        }
    }

    __syncthreads();
    for (int i = tid; i < 1023; i += 256) atomicAdd(&gT[i], Tacc[i]);
    for (int i = tid; i < 2046; i += 256) atomicAdd(&gU[i], Uacc[i]);
}

// ---------------- regularizer scalar ----------------
__global__ void reg_kernel(const float* __restrict__ gT, const float* __restrict__ gU,
                           float* __restrict__ out) {
    float local = 0.0f;
    int toff = 0, uoff = 0;
#pragma unroll
    for (int d = 0; d < DEPTH; d++) {
        const int nout = 2 << d;
        const float factor = LAMBDA * exp2f(-(float)d);
        for (int k = threadIdx.x; k < nout; k += 256) {
            float den = gT[toff + (k >> 1)] + 1e-8f;
            float alpha = gU[uoff + k] / den;
            local += factor * (-0.5f) * (logf(alpha) + logf(1.0f - alpha));
        }
        toff += (1 << d);
        uoff += nout;
    }
    __shared__ float red[256];
    red[threadIdx.x] = local;
    __syncthreads();
    for (int s = 128; s > 0; s >>= 1) {
        if (threadIdx.x < s) red[threadIdx.x] += red[threadIdx.x + s];
        __syncthreads();
    }
    if (threadIdx.x == 0) out[0] = red[0];
}

// ---------------- launch ----------------
extern "C" void kernel_launch(void* const* d_in, const int* in_sizes, int n_in,
                              void* d_out, int out_size) {
    const float* X  = (const float*)d_in[0];   // [16384, 1024]
    const float* Wi = (const float*)d_in[1];   // [1023, 1025]
    const float* Wl = (const float*)d_in[2];   // [1000, 1024]
    float* out = (float*)d_out;

    __nv_bfloat16 *xhi, *xlo, *phip, *plop, *whi, *wlo, *lhi, *llo;
    float *s_p, *bias_p, *t_p, *u_p;
    cudaGetSymbolAddress((void**)&xhi,  g_Xhi);
    cudaGetSymbolAddress((void**)&xlo,  g_Xlo);
    cudaGetSymbolAddress((void**)&phip, g_Phi);
    cudaGetSymbolAddress((void**)&plop, g_Plo);
    cudaGetSymbolAddress((void**)&whi,  g_Whi);
    cudaGetSymbolAddress((void**)&wlo,  g_Wlo);
    cudaGetSymbolAddress((void**)&lhi,  g_Lhi);
    cudaGetSymbolAddress((void**)&llo,  g_Llo);
    cudaGetSymbolAddress((void**)&s_p,  g_s);
    cudaGetSymbolAddress((void**)&bias_p, g_bias);
    cudaGetSymbolAddress((void**)&t_p,  g_T);
    cudaGetSymbolAddress((void**)&u_p,  g_U);

    cudaFuncSetAttribute(mma_gemm_kernel<true>,
                         cudaFuncAttributeMaxDynamicSharedMemorySize, DYN_SMEM);
    cudaFuncSetAttribute(mma_gemm_kernel<false>,
                         cudaFuncAttributeMaxDynamicSharedMemorySize, DYN_SMEM);

    // 1. split inputs into bf16 hi/lo (+ zero T/U inside repack_w)
    split_x_kernel<<<(B_SZ * KDIM / 4 + 255) / 256, 256>>>(X, xhi, xlo);
    repack_w_kernel<<<(KDIM * KDIM + 255) / 256, 256>>>(Wi, whi, wlo, bias_p, t_p, u_p);
    repack_l_kernel<<<(KDIM * KDIM + 255) / 256, 256>>>(Wl, lhi, llo);

    // 2. GEMM1 + bias + sigmoid -> g_s (fp32, ld=1024)
    {
        dim3 grid(8, B_SZ / 128);   // (8, 128)
        mma_gemm_kernel<true><<<grid, 256, DYN_SMEM>>>(
            xhi, xlo, whi, wlo, bias_p, s_p, 1024, 1024);
    }

    // 3. path probs (bf16 hi/lo) + regularizer partial sums
    path_kernel<<<B_SZ / SAMPLES_PER_BLOCK, 256>>>(s_p, phip, plop, t_p, u_p);

    // 4. GEMM2: predictions = path @ W_leaf^T -> d_out (ld=1000, clip 1000)
    {
        dim3 grid(8, B_SZ / 128);
        mma_gemm_kernel<false><<<grid, 256, DYN_SMEM>>>(
            phip, plop, lhi, llo, nullptr, out, OUT_DIM, OUT_DIM);
    }

    // 5. regularizer scalar -> last output element
    reg_kernel<<<1, 256>>>(t_p, u_p, out + (out_size - 1));
}

// round 7
// speedup vs baseline: 3.8399x; 1.3490x over previous
#include <cuda_runtime.h>
#include <cuda_bf16.h>
#include <cstdint>
#include <math.h>

// ---------------- problem constants ----------------
#define B_SZ      16384
#define KDIM      1024
#define OUT_DIM   1000
#define N_INT     1023
#define DEPTH     10
#define LAMBDA    1e-3f

// ---------------- scratch (device globals) ----------------
__device__ __nv_bfloat16 g_Xhi[(size_t)B_SZ * KDIM];
__device__ __nv_bfloat16 g_Xlo[(size_t)B_SZ * KDIM];
__device__ __nv_bfloat16 g_Phi[(size_t)B_SZ * KDIM];
__device__ __nv_bfloat16 g_Plo[(size_t)B_SZ * KDIM];
__device__ __nv_bfloat16 g_Whi[(size_t)KDIM * KDIM];
__device__ __nv_bfloat16 g_Wlo[(size_t)KDIM * KDIM];
__device__ __nv_bfloat16 g_Lhi[(size_t)KDIM * KDIM];
__device__ __nv_bfloat16 g_Llo[(size_t)KDIM * KDIM];
__device__ float g_s[(size_t)B_SZ * KDIM];
__device__ float g_bias[KDIM];
__device__ float g_T[1023];
__device__ float g_U[2046];

// ---------------- PTX helpers (sm_80-class features only) ----------------
__device__ __forceinline__ uint32_t smem_u32(const void* p) {
    uint32_t a;
    asm("{ .reg .u64 t; cvta.to.shared.u64 t, %1; cvt.u32.u64 %0, t; }" : "=r"(a) : "l"(p));
    return a;
}

#define CP_ASYNC16(dst, src) \
    asm volatile("cp.async.cg.shared.global [%0], [%1], 16;" :: "r"(dst), "l"(src))
#define CP_COMMIT() asm volatile("cp.async.commit_group;" ::: "memory")
#define CP_WAIT(n)  asm volatile("cp.async.wait_group %0;" :: "n"(n) : "memory")

#define LDMX4(r0, r1, r2, r3, addr) \
    asm volatile("ldmatrix.sync.aligned.m8n8.x4.shared.b16 {%0,%1,%2,%3}, [%4];" \
        : "=r"(r0), "=r"(r1), "=r"(r2), "=r"(r3) : "r"(addr))

#define MMA16816(d, a, b) \
    asm volatile("mma.sync.aligned.m16n8k16.row.col.f32.bf16.bf16.f32 " \
        "{%0,%1,%2,%3}, {%4,%5,%6,%7}, {%8,%9}, {%0,%1,%2,%3};" \
        : "+f"((d)[0]), "+f"((d)[1]), "+f"((d)[2]), "+f"((d)[3]) \
        : "r"((a)[0]), "r"((a)[1]), "r"((a)[2]), "r"((a)[3]), \
          "r"((b)[0]), "r"((b)[1]))

// ---------------- fp32 -> bf16 hi/lo split ----------------
__device__ __forceinline__ void split2(float x, __nv_bfloat16& h, __nv_bfloat16& l) {
    h = __float2bfloat16(x);
    l = __float2bfloat16(x - __bfloat162float(h));
}

__global__ void split_x_kernel(const float* __restrict__ src,
                               __nv_bfloat16* __restrict__ hi,
                               __nv_bfloat16* __restrict__ lo) {
    size_t i = (size_t)blockIdx.x * blockDim.x + threadIdx.x;  // quad index
    float4 v = ((const float4*)src)[i];
    __nv_bfloat16 h0, h1, h2, h3, l0, l1, l2, l3;
    split2(v.x, h0, l0); split2(v.y, h1, l1); split2(v.z, h2, l2); split2(v.w, h3, l3);
    ((__nv_bfloat162*)hi)[2 * i]     = __nv_bfloat162(h0, h1);
    ((__nv_bfloat162*)hi)[2 * i + 1] = __nv_bfloat162(h2, h3);
    ((__nv_bfloat162*)lo)[2 * i]     = __nv_bfloat162(l0, l1);
    ((__nv_bfloat162*)lo)[2 * i + 1] = __nv_bfloat162(l2, l3);
}

// also zeroes the T/U accumulators
__global__ void repack_w_kernel(const float* __restrict__ Wi,
                                __nv_bfloat16* __restrict__ hi,
                                __nv_bfloat16* __restrict__ lo,
                                float* __restrict__ bias,
                                float* __restrict__ t, float* __restrict__ u) {
    int idx = blockIdx.x * blockDim.x + threadIdx.x;
    if (idx < KDIM * KDIM) {
        int n = idx >> 10, k = idx & 1023;
        float v = (n < N_INT) ? Wi[(size_t)n * 1025 + 1 + k] : 0.0f;
        __nv_bfloat16 h, l; split2(v, h, l);
        hi[idx] = h; lo[idx] = l;
    }
    if (idx < KDIM) bias[idx] = (idx < N_INT) ? Wi[(size_t)idx * 1025] : 0.0f;
    if (idx < 1023) t[idx] = 0.0f;
    if (idx < 2046) u[idx] = 0.0f;
}

__global__ void repack_l_kernel(const float* __restrict__ Wl,
                                __nv_bfloat16* __restrict__ hi,
                                __nv_bfloat16* __restrict__ lo) {
    int idx = blockIdx.x * blockDim.x + threadIdx.x;
    if (idx < KDIM * KDIM) {
        int n = idx >> 10, k = idx & 1023;
        float v = (n < OUT_DIM) ? Wl[(size_t)n * KDIM + k] : 0.0f;
        __nv_bfloat16 h, l; split2(v, h, l);
        hi[idx] = h; lo[idx] = l;
    }
}

// ---------------- mma.sync GEMM: C[M,N] = A * B^T (3-term bf16 emulation) ---
// CTA tile 128x128, BK=32, 2-stage cp.async ring, 256 threads (8 warps 4Mx2N,
// warp tile 32x64), 2 CTAs/SM. ONE __syncthreads per BK=32 chunk; two k-steps
// run barrier-free so warps stagger and keep the tensor pipe fed.
#define ROWB        80                    // 64B data + 16B pad (conflict-free)
#define TROWS       128
#define OFF_AHI     0
#define OFF_ALO     (TROWS * ROWB)        // 10240
#define OFF_BHI     (2 * TROWS * ROWB)    // 20480
#define OFF_BLO     (3 * TROWS * ROWB)    // 30720
#define STAGE_BYTES (4 * TROWS * ROWB)    // 40960
#define NSTAGE      2
#define NCHUNK      32                    // K=1024 / BK=32
#define DYN_SMEM    (NSTAGE * STAGE_BYTES + 512)

__device__ __forceinline__ void load_stage(
        const __nv_bfloat16* __restrict__ Ahi, const __nv_bfloat16* __restrict__ Alo,
        const __nv_bfloat16* __restrict__ Bhi, const __nv_bfloat16* __restrict__ Blo,
        int m0, int n0, int chunk, uint32_t sb, int tid) {
    const int r = tid >> 2;            // 0..63
    const int c = tid & 3;             // 16B quarter of the 64B row
    const int kk = chunk * 32 + c * 8; // bf16 element offset
    const uint32_t doff = (uint32_t)r * ROWB + (uint32_t)c * 16;
#pragma unroll
    for (int h = 0; h < 2; h++) {
        const int rr = r + h * 64;
        const uint32_t d = sb + doff + (uint32_t)(h * 64 * ROWB);
        CP_ASYNC16(d + OFF_AHI, Ahi + (size_t)(m0 + rr) * KDIM + kk);
        CP_ASYNC16(d + OFF_ALO, Alo + (size_t)(m0 + rr) * KDIM + kk);
        CP_ASYNC16(d + OFF_BHI, Bhi + (size_t)(n0 + rr) * KDIM + kk);
        CP_ASYNC16(d + OFF_BLO, Blo + (size_t)(n0 + rr) * KDIM + kk);
    }
}

template<bool SIG>
__global__ void __launch_bounds__(256, 2)
mma_gemm_kernel(const __nv_bfloat16* __restrict__ Ahi, const __nv_bfloat16* __restrict__ Alo,
                const __nv_bfloat16* __restrict__ Bhi, const __nv_bfloat16* __restrict__ Blo,
                const float* __restrict__ bias, float* __restrict__ C,
                int ldc, int nclip) {
    extern __shared__ char sm[];
    const uint32_t s0 = smem_u32(sm);
    float* bias_sh = (float*)(sm + NSTAGE * STAGE_BYTES);

    const int tid  = threadIdx.x;
    const int lane = tid & 31;
    const int wid  = tid >> 5;
    const int wm   = wid & 3;    // 4 M-warps of 32 rows
    const int wn   = wid >> 2;   // 2 N-warps of 64 cols
    const int m0   = blockIdx.y * 128;
    const int n0   = blockIdx.x * 128;

    if (SIG && tid < 128) bias_sh[tid] = bias[n0 + tid];

    float acc[2][8][4];
#pragma unroll
    for (int mi = 0; mi < 2; mi++)
#pragma unroll
        for (int ni = 0; ni < 8; ni++)
#pragma unroll
            for (int j = 0; j < 4; j++) acc[mi][ni][j] = 0.0f;

    // ldmatrix per-thread address components
    const uint32_t a_off = (uint32_t)(wm * 32 + (lane & 15)) * ROWB
                         + (uint32_t)(lane >> 4) * 16;
    const uint32_t b_off = (uint32_t)(wn * 64 + ((lane >> 4) & 1) * 8 + (lane & 7)) * ROWB
                         + (uint32_t)((lane >> 3) & 1) * 16;

    // prologue: stage 0
    load_stage(Ahi, Alo, Bhi, Blo, m0, n0, 0, s0, tid);
    CP_COMMIT();

    for (int s = 0; s < NCHUNK; s++) {
        CP_WAIT(0);          // stage s landed (this thread)
        __syncthreads();     // stage s visible CTA-wide; stage s-1 reads all done

        const uint32_t sb = s0 + (uint32_t)(s & 1) * STAGE_BYTES;

#pragma unroll
        for (int ks = 0; ks < 2; ks++) {
            uint32_t ah[2][4], al[2][4];
#pragma unroll
            for (int mi = 0; mi < 2; mi++) {
                const uint32_t ao = sb + a_off + (uint32_t)(mi * 16 * ROWB)
                                  + (uint32_t)(ks * 32);
                LDMX4(ah[mi][0], ah[mi][1], ah[mi][2], ah[mi][3], ao + OFF_AHI);
                LDMX4(al[mi][0], al[mi][1], al[mi][2], al[mi][3], ao + OFF_ALO);
            }
#pragma unroll
            for (int half = 0; half < 2; half++) {
                uint32_t bh[4][2], bl[4][2];
#pragma unroll
                for (int p = 0; p < 2; p++) {
                    const int pj = half * 2 + p;
                    const uint32_t bo = sb + b_off + (uint32_t)(pj * 16 * ROWB)
                                      + (uint32_t)(ks * 32);
                    LDMX4(bh[2 * p][0], bh[2 * p][1], bh[2 * p + 1][0], bh[2 * p + 1][1],
                          bo + OFF_BHI);
                    LDMX4(bl[2 * p][0], bl[2 * p][1], bl[2 * p + 1][0], bl[2 * p + 1][1],
                          bo + OFF_BLO);
                }
#pragma unroll
                for (int mi = 0; mi < 2; mi++)
#pragma unroll
                    for (int nj = 0; nj < 4; nj++) {
                        float* a4 = acc[mi][half * 4 + nj];
                        MMA16816(a4, ah[mi], bh[nj]);
                        MMA16816(a4, ah[mi], bl[nj]);
                        MMA16816(a4, al[mi], bh[nj]);
                    }
            }
            // prefetch next stage between k-steps: its ~600cyc latency hides
            // under the remaining ~1500cyc of this chunk's MMAs.
            if (ks == 0 && s + 1 < NCHUNK) {
                load_stage(Ahi, Alo, Bhi, Blo, m0, n0, s + 1,
                           s0 + (uint32_t)((s + 1) & 1) * STAGE_BYTES, tid);
                CP_COMMIT();
            }
        }
    }

    // epilogue: direct register -> global stores (float2, 8B aligned)
    const int tr = lane >> 2;
    const int tc = (lane & 3) * 2;
#pragma unroll
    for (int mi = 0; mi < 2; mi++) {
#pragma unroll
        for (int ni = 0; ni < 8; ni++) {
            const int row = m0 + wm * 32 + mi * 16 + tr;
            const int col = n0 + wn * 64 + ni * 8 + tc;
            float v0 = acc[mi][ni][0], v1 = acc[mi][ni][1];
            float v2 = acc[mi][ni][2], v3 = acc[mi][ni][3];
            if (SIG) {
                const float b0 = bias_sh[col - n0];
                const float b1 = bias_sh[col - n0 + 1];
                v0 = 1.0f / (1.0f + expf(-(v0 + b0)));
                v1 = 1.0f / (1.0f + expf(-(v1 + b1)));
                v2 = 1.0f / (1.0f + expf(-(v2 + b0)));
                v3 = 1.0f / (1.0f + expf(-(v3 + b1)));
            }
            if (col < nclip) {  // col even, nclip even -> pair never straddles
                *(float2*)&C[(size_t)row * ldc + col]       = make_float2(v0, v1);
                *(float2*)&C[(size_t)(row + 8) * ldc + col] = make_float2(v2, v3);
            }
        }
    }
}

// ---------------- path + regularizer partial sums ----------------
#define SAMPLES_PER_BLOCK 16

__global__ void __launch_bounds__(256)
path_kernel(const float* __restrict__ s_g,
            __nv_bfloat16* __restrict__ phi, __nv_bfloat16* __restrict__ plo,
            float* __restrict__ gT, float* __restrict__ gU) {
    __shared__ float s_sh[1024];
    __shared__ float bufA[1024];
    __shared__ float bufB[1024];
    __shared__ float Tacc[1023];
    __shared__ float Uacc[2046];

    const int tid = threadIdx.x;
    for (int i = tid; i < 1023; i += 256) Tacc[i] = 0.0f;
    for (int i = tid; i < 2046; i += 256) Uacc[i] = 0.0f;

    const int base = blockIdx.x * SAMPLES_PER_BLOCK;

    for (int s = 0; s < SAMPLES_PER_BLOCK; s++) {
        const int b = base + s;
        __syncthreads();
        for (int i = tid; i < 1024; i += 256)
            s_sh[i] = s_g[(size_t)b * 1024 + i];
        if (tid == 0) bufA[0] = 1.0f;
        __syncthreads();

        float* cur = bufA;
        float* nxt = bufB;
        int toff = 0, uoff = 0;

#pragma unroll
        for (int d = 0; d < DEPTH; d++) {
            const int nout = 2 << d;
            const int nbase = (1 << d) - 1;
            for (int k = tid; k < nout; k += 256) {
                float sv = s_sh[nbase + (k >> 1)];
                float lp = (k & 1) ? (1.0f - sv) : sv;
                float nk = cur[k >> 1] * lp;
                nxt[k] = nk;
                int p = k >> 1;
                float svp = s_sh[nbase + (p >> 1)];
                float lpp = (p & 1) ? (1.0f - svp) : svp;
                float pn = cur[p >> 1] * lpp;
                Uacc[uoff + k] += lp * pn;
                if (k < (nout >> 1)) Tacc[toff + k] += nk;
            }
            __syncthreads();
            toff += nout >> 1;
            uoff += nout;
            float* t = cur; cur = nxt; nxt = t;
        }

        for (int l = tid; l < 1024; l += 256) {
            float p = cur[l];
            __nv_bfloat16 h, lo; split2(p, h, lo);
            phi[(size_t)b * 1024 + l] = h;
            plo[(size_t)b * 1024 + l] = lo;
        }
    }

    __syncthreads();
    for (int i = tid; i < 1023; i += 256) atomicAdd(&gT[i], Tacc[i]);
    for (int i = tid; i < 2046; i += 256) atomicAdd(&gU[i], Uacc[i]);
}

// ---------------- regularizer scalar ----------------
__global__ void reg_kernel(const float* __restrict__ gT, const float* __restrict__ gU,
                           float* __restrict__ out) {
    float local = 0.0f;
    int toff = 0, uoff = 0;
#pragma unroll
    for (int d = 0; d < DEPTH; d++) {
        const int nout = 2 << d;
        const float factor = LAMBDA * exp2f(-(float)d);
        for (int k = threadIdx.x; k < nout; k += 256) {
            float den = gT[toff + (k >> 1)] + 1e-8f;
            float alpha = gU[uoff + k] / den;
            local += factor * (-0.5f) * (logf(alpha) + logf(1.0f - alpha));
        }
        toff += (1 << d);
        uoff += nout;
    }
    __shared__ float red[256];
    red[threadIdx.x] = local;
    __syncthreads();
    for (int s = 128; s > 0; s >>= 1) {
        if (threadIdx.x < s) red[threadIdx.x] += red[threadIdx.x + s];
        __syncthreads();
    }
    if (threadIdx.x == 0) out[0] = red[0];
}

// ---------------- launch ----------------
extern "C" void kernel_launch(void* const* d_in, const int* in_sizes, int n_in,
                              void* d_out, int out_size) {
    const float* X  = (const float*)d_in[0];   // [16384, 1024]
    const float* Wi = (const float*)d_in[1];   // [1023, 1025]
    const float* Wl = (const float*)d_in[2];   // [1000, 1024]
    float* out = (float*)d_out;

    __nv_bfloat16 *xhi, *xlo, *phip, *plop, *whi, *wlo, *lhi, *llo;
    float *s_p, *bias_p, *t_p, *u_p;
    cudaGetSymbolAddress((void**)&xhi,  g_Xhi);
    cudaGetSymbolAddress((void**)&xlo,  g_Xlo);
    cudaGetSymbolAddress((void**)&phip, g_Phi);
    cudaGetSymbolAddress((void**)&plop, g_Plo);
    cudaGetSymbolAddress((void**)&whi,  g_Whi);
    cudaGetSymbolAddress((void**)&wlo,  g_Wlo);
    cudaGetSymbolAddress((void**)&lhi,  g_Lhi);
    cudaGetSymbolAddress((void**)&llo,  g_Llo);
    cudaGetSymbolAddress((void**)&s_p,  g_s);
    cudaGetSymbolAddress((void**)&bias_p, g_bias);
    cudaGetSymbolAddress((void**)&t_p,  g_T);
    cudaGetSymbolAddress((void**)&u_p,  g_U);

    cudaFuncSetAttribute(mma_gemm_kernel<true>,
                         cudaFuncAttributeMaxDynamicSharedMemorySize, DYN_SMEM);
    cudaFuncSetAttribute(mma_gemm_kernel<false>,
                         cudaFuncAttributeMaxDynamicSharedMemorySize, DYN_SMEM);

    // 1. split inputs into bf16 hi/lo (+ zero T/U inside repack_w)
    split_x_kernel<<<(B_SZ * KDIM / 4 + 255) / 256, 256>>>(X, xhi, xlo);
    repack_w_kernel<<<(KDIM * KDIM + 255) / 256, 256>>>(Wi, whi, wlo, bias_p, t_p, u_p);
    repack_l_kernel<<<(KDIM * KDIM + 255) / 256, 256>>>(Wl, lhi, llo);

    // 2. GEMM1 + bias + sigmoid -> g_s (fp32, ld=1024)
    {
        dim3 grid(8, B_SZ / 128);   // (8, 128)
        mma_gemm_kernel<true><<<grid, 256, DYN_SMEM>>>(
            xhi, xlo, whi, wlo, bias_p, s_p, 1024, 1024);
    }

    // 3. path probs (bf16 hi/lo) + regularizer partial sums
    path_kernel<<<B_SZ / SAMPLES_PER_BLOCK, 256>>>(s_p, phip, plop, t_p, u_p);

    // 4. GEMM2: predictions = path @ W_leaf^T -> d_out (ld=1000, clip 1000)
    {
        dim3 grid(8, B_SZ / 128);
        mma_gemm_kernel<false><<<grid, 256, DYN_SMEM>>>(
            phip, plop, lhi, llo, nullptr, out, OUT_DIM, OUT_DIM);
    }

    // 5. regularizer scalar -> last output element
    reg_kernel<<<1, 256>>>(t_p, u_p, out + (out_size - 1));
}